// round 5
// baseline (speedup 1.0000x reference)
#include <cuda_runtime.h>

namespace {
constexpr int B  = 2;
constexpr int S  = 2048;
constexpr int H  = 16;
constexpr int D  = 64;
constexpr int TQ = 64;
constexpr int TK = 64;
constexpr int NT = 256;
constexpr int HD = H * D;
constexpr int PS_STRIDE = 68;                         // floats; 272B rows: 16B-aligned, conflict-free
constexpr int SMEM_BYTES = 3 * 16384 + TQ * PS_STRIDE * 4;  // 66560
}

// ---- packed f32x2 helpers (Blackwell FFMA2 path) ----
__device__ __forceinline__ unsigned long long f2fma(unsigned long long a,
                                                    unsigned long long b,
                                                    unsigned long long c) {
    unsigned long long d;
    asm("fma.rn.f32x2 %0, %1, %2, %3;" : "=l"(d) : "l"(a), "l"(b), "l"(c));
    return d;
}
__device__ __forceinline__ unsigned long long f2mul(unsigned long long a,
                                                    unsigned long long b) {
    unsigned long long d;
    asm("mul.rn.f32x2 %0, %1, %2;" : "=l"(d) : "l"(a), "l"(b));
    return d;
}
__device__ __forceinline__ unsigned long long pack2(float lo, float hi) {
    unsigned long long d;
    asm("mov.b64 %0, {%1, %2};" : "=l"(d) : "f"(lo), "f"(hi));
    return d;
}
__device__ __forceinline__ float2 unpack2(unsigned long long p) {
    float lo, hi;
    asm("mov.b64 {%0, %1}, %2;" : "=f"(lo), "=f"(hi) : "l"(p));
    return make_float2(lo, hi);
}

// Flash-attention fp32 kernel, f32x2-packed math.
// smem (dynamic):
//   qs2[32][64] u64 : Q packed over d-pairs, pre-scaled by 8      (16 KB)
//   ks2[32][64] u64 : K packed over d-pairs                        (16 KB)
//   vs2[32][64] u64 : V packed over kk-pairs (vs2[kkp][d])         (16 KB)
//   ps [64][68] f32 : P tile, padded stride -> conflict-free reads (17 KB)
__global__ void __launch_bounds__(NT, 2)
attn_f32x2_kernel(const float* __restrict__ gq, const float* __restrict__ gk,
                  const float* __restrict__ gv, const float* __restrict__ gbias,
                  const int*   __restrict__ gmask, float* __restrict__ gout)
{
    extern __shared__ char smem[];
    unsigned long long* qs2 = reinterpret_cast<unsigned long long*>(smem);
    unsigned long long* ks2 = reinterpret_cast<unsigned long long*>(smem + 16384);
    unsigned long long* vs2 = reinterpret_cast<unsigned long long*>(smem + 32768);
    float*              ps  = reinterpret_cast<float*>(smem + 49152);

    const int tid = threadIdx.x;
    const int tx  = tid & 15;          // col group (4 score cols / 4 d cols)
    const int ty  = tid >> 4;          // row group (4 rows)
    const int bh  = blockIdx.x;
    const int b   = bh >> 4;
    const int h   = bh & 15;
    const int q0  = blockIdx.y * TQ;

    // staging lane map for Q/K (transposed, d-pair packed)
    const int cc = (tid & 15) | ((tid >> 6) << 4);   // row 0..63
    const int d0 = ((tid >> 4) & 3) << 2;            // 0,4,8,12
    // staging lane map for V (kk-pair interleave)
    const int vkkp = tid >> 3;                       // 0..31
    const int vdb  = (tid & 7) << 3;                 // 0..56

    // ---- stage Q once (packed over d-pairs, scaled by 8; exact in fp32) ----
    {
        const float* qb = gq + ((size_t)(b * S + q0) * H + h) * D;
        #pragma unroll
        for (int rep = 0; rep < 4; rep++) {
            const int dv = d0 + (rep << 4);
            float4 t = *reinterpret_cast<const float4*>(qb + (size_t)cc * HD + dv);
            qs2[(dv >> 1) * TQ + cc]       = pack2(t.x * 8.0f, t.y * 8.0f);
            qs2[((dv >> 1) + 1) * TQ + cc] = pack2(t.z * 8.0f, t.w * 8.0f);
        }
    }

    unsigned long long o2[4][4];
    #pragma unroll
    for (int i = 0; i < 4; i++)
        #pragma unroll
        for (int j = 0; j < 4; j++) o2[i][j] = 0ull;
    float mrow[4] = {-1e30f, -1e30f, -1e30f, -1e30f};
    float lrow[4] = {0.f, 0.f, 0.f, 0.f};

    const float* kb0 = gk + ((size_t)(b * S) * H + h) * D;
    const float* vb0 = gv + ((size_t)(b * S) * H + h) * D;

    for (int k0 = 0; k0 < S; k0 += TK) {
        __syncthreads();   // prior tile done with ks2/vs2/ps

        // ---- stage K (d-pair packed) ----
        {
            const float* kb = kb0 + (size_t)k0 * HD;
            #pragma unroll
            for (int rep = 0; rep < 4; rep++) {
                const int dv = d0 + (rep << 4);
                float4 t = *reinterpret_cast<const float4*>(kb + (size_t)cc * HD + dv);
                ks2[(dv >> 1) * TK + cc]       = pack2(t.x, t.y);
                ks2[((dv >> 1) + 1) * TK + cc] = pack2(t.z, t.w);
            }
        }
        // ---- stage V (kk-pair packed: vs2[kkp][d] = (v[2kkp][d], v[2kkp+1][d])) ----
        {
            const float* r0 = vb0 + (size_t)(k0 + 2 * vkkp) * HD + vdb;
            const float* r1 = r0 + HD;
            float4 a0 = *reinterpret_cast<const float4*>(r0);
            float4 a1 = *reinterpret_cast<const float4*>(r0 + 4);
            float4 c0 = *reinterpret_cast<const float4*>(r1);
            float4 c1 = *reinterpret_cast<const float4*>(r1 + 4);
            unsigned long long* dst = &vs2[vkkp * 64 + vdb];
            dst[0] = pack2(a0.x, c0.x); dst[1] = pack2(a0.y, c0.y);
            dst[2] = pack2(a0.z, c0.z); dst[3] = pack2(a0.w, c0.w);
            dst[4] = pack2(a1.x, c1.x); dst[5] = pack2(a1.y, c1.y);
            dst[6] = pack2(a1.z, c1.z); dst[7] = pack2(a1.w, c1.w);
        }
        __syncthreads();

        // ---- S = (Q*8) K^T, packed over d-pairs: 16 FFMA2 + 4 LDS.128 per dp ----
        unsigned long long s2[4][4];
        #pragma unroll
        for (int i = 0; i < 4; i++)
            #pragma unroll
            for (int j = 0; j < 4; j++) s2[i][j] = 0ull;

        #pragma unroll 4
        for (int dp = 0; dp < 32; dp++) {
            ulonglong2 qa  = *reinterpret_cast<const ulonglong2*>(&qs2[dp * TQ + (ty << 2)]);
            ulonglong2 qb2 = *reinterpret_cast<const ulonglong2*>(&qs2[dp * TQ + (ty << 2) + 2]);
            ulonglong2 ka  = *reinterpret_cast<const ulonglong2*>(&ks2[dp * TK + (tx << 2)]);
            ulonglong2 kb2 = *reinterpret_cast<const ulonglong2*>(&ks2[dp * TK + (tx << 2) + 2]);
            const unsigned long long qv[4] = {qa.x, qa.y, qb2.x, qb2.y};
            const unsigned long long kv[4] = {ka.x, ka.y, kb2.x, kb2.y};
            #pragma unroll
            for (int i = 0; i < 4; i++)
                #pragma unroll
                for (int j = 0; j < 4; j++)
                    s2[i][j] = f2fma(qv[i], kv[j], s2[i][j]);
        }

        // ---- bias add, mask->0, online softmax, write P ----
        #pragma unroll
        for (int i = 0; i < 4; i++) {
            const int row = q0 + (ty << 2) + i;
            const float4 bv = *reinterpret_cast<const float4*>(
                gbias + ((size_t)bh * S + row) * S + k0 + (tx << 2));
            const int4 mv = *reinterpret_cast<const int4*>(
                gmask + ((size_t)b * S + row) * S + k0 + (tx << 2));

            const float2 u0 = unpack2(s2[i][0]);
            const float2 u1 = unpack2(s2[i][1]);
            const float2 u2 = unpack2(s2[i][2]);
            const float2 u3 = unpack2(s2[i][3]);
            float sv[4];
            sv[0] = mv.x ? 0.0f : (u0.x + u0.y) + bv.x;
            sv[1] = mv.y ? 0.0f : (u1.x + u1.y) + bv.y;
            sv[2] = mv.z ? 0.0f : (u2.x + u2.y) + bv.z;
            sv[3] = mv.w ? 0.0f : (u3.x + u3.y) + bv.w;

            float mx = fmaxf(fmaxf(sv[0], sv[1]), fmaxf(sv[2], sv[3]));
            #pragma unroll
            for (int off = 8; off; off >>= 1)
                mx = fmaxf(mx, __shfl_xor_sync(0xffffffffu, mx, off));
            const float mnew = fmaxf(mrow[i], mx);
            const float corr = __expf(mrow[i] - mnew);
            mrow[i] = mnew;

            float rs = 0.f;
            #pragma unroll
            for (int j = 0; j < 4; j++) {
                sv[j] = __expf(sv[j] - mnew);
                rs += sv[j];
            }
            #pragma unroll
            for (int off = 8; off; off >>= 1)
                rs += __shfl_xor_sync(0xffffffffu, rs, off);
            lrow[i] = lrow[i] * corr + rs;

            const unsigned long long corr2 = pack2(corr, corr);
            #pragma unroll
            for (int j = 0; j < 4; j++) o2[i][j] = f2mul(o2[i][j], corr2);

            *reinterpret_cast<float4*>(&ps[((ty << 2) + i) * PS_STRIDE + (tx << 2)]) =
                make_float4(sv[0], sv[1], sv[2], sv[3]);
        }
        __syncthreads();   // all P written before PV reads

        // ---- O += P V, packed over kk-pairs: 16 FFMA2 + 4 LDS.64 + 2 LDS.128 per kkp ----
        #pragma unroll 4
        for (int kkp = 0; kkp < 32; kkp++) {
            ulonglong2 va  = *reinterpret_cast<const ulonglong2*>(&vs2[kkp * 64 + (tx << 2)]);
            ulonglong2 vb2 = *reinterpret_cast<const ulonglong2*>(&vs2[kkp * 64 + (tx << 2) + 2]);
            const unsigned long long vv[4] = {va.x, va.y, vb2.x, vb2.y};
            #pragma unroll
            for (int i = 0; i < 4; i++) {
                const unsigned long long p2 = *reinterpret_cast<const unsigned long long*>(
                    &ps[((ty << 2) + i) * PS_STRIDE + 2 * kkp]);
                #pragma unroll
                for (int j = 0; j < 4; j++)
                    o2[i][j] = f2fma(p2, vv[j], o2[i][j]);
            }
        }
    }

    // ---- epilogue: combine halves, normalize, store [B,S,H,D] ----
    #pragma unroll
    for (int i = 0; i < 4; i++) {
        const float inv = 1.0f / lrow[i];
        const int row = q0 + (ty << 2) + i;
        const float2 w0 = unpack2(o2[i][0]);
        const float2 w1 = unpack2(o2[i][1]);
        const float2 w2 = unpack2(o2[i][2]);
        const float2 w3 = unpack2(o2[i][3]);
        const float4 o = make_float4((w0.x + w0.y) * inv, (w1.x + w1.y) * inv,
                                     (w2.x + w2.y) * inv, (w3.x + w3.y) * inv);
        *reinterpret_cast<float4*>(
            gout + ((size_t)(b * S + row) * H + h) * D + (tx << 2)) = o;
    }
}

extern "C" void kernel_launch(void* const* d_in, const int* in_sizes, int n_in,
                              void* d_out, int out_size) {
    const float* q    = (const float*)d_in[0];
    const float* k    = (const float*)d_in[1];
    const float* v    = (const float*)d_in[2];
    const float* bias = (const float*)d_in[3];
    const int*   mask = (const int*)d_in[4];
    float* out = (float*)d_out;

    cudaFuncSetAttribute(attn_f32x2_kernel,
                         cudaFuncAttributeMaxDynamicSharedMemorySize, SMEM_BYTES);
    dim3 grid(B * H, S / TQ);
    attn_f32x2_kernel<<<grid, NT, SMEM_BYTES>>>(q, k, v, bias, mask, out);
}

// round 6
// speedup vs baseline: 1.3527x; 1.3527x over previous
#include <cuda_runtime.h>

namespace {
constexpr int B  = 2;
constexpr int S  = 2048;
constexpr int H  = 16;
constexpr int D  = 64;
constexpr int TQ = 64;
constexpr int TK = 64;
constexpr int NT = 256;
constexpr int HD = H * D;
constexpr int PSS = 68;   // P row stride in floats: rows 4 apart -> +16 banks -> conflict-free
constexpr int SMEM_BYTES = (3 * D * 64 + TQ * PSS) * 4;   // 48KB + 17KB = 66816
}

// Flash-attention fp32, 4x4 micro-tiles, conflict-engineered smem.
// dynamic smem:
//   qs[d][row]  64x64 f32 : Q transposed, pre-scaled by 8     (16 KB)
//   ks[d][col]  64x64 f32 : K transposed                       (16 KB)
//   vs[kk][d]   64x64 f32 : V natural                          (16 KB)
//   ps[row][68] f32       : P tile, padded stride              (17 KB)
__global__ void __launch_bounds__(NT, 3)
attn_fp32_kernel(const float* __restrict__ gq, const float* __restrict__ gk,
                 const float* __restrict__ gv, const float* __restrict__ gbias,
                 const int*   __restrict__ gmask, float* __restrict__ gout)
{
    extern __shared__ float smem[];
    float* qs = smem;                 // [64][64]
    float* ks = smem + 4096;          // [64][64]
    float* vs = smem + 8192;          // [64][64]
    float* ps = smem + 12288;         // [64][68]

    const int tid = threadIdx.x;
    const int tx  = tid & 15;         // col group (4 cols)
    const int ty  = tid >> 4;         // row group (4 rows)
    const int bh  = blockIdx.x;       // b*H + h  (bias [B,H,S,S] layout)
    const int b   = bh >> 4;
    const int h   = bh & 15;
    const int q0  = blockIdx.y * TQ;

    // staging lane map (transposed Q/K): cc varies across lanes -> <=2-way STS conflict,
    // lane pairs (l, l+16) cover contiguous 32B gmem sectors.
    const int cc = (tid & 15) | ((tid >> 6) << 4);   // 0..63
    const int d0 = ((tid >> 4) & 3) << 2;            // 0,4,8,12

    // ---- stage Q once (transposed, pre-scaled by 8; exact in fp32) ----
    {
        const float* qb = gq + ((size_t)(b * S + q0) * H + h) * D;
        #pragma unroll
        for (int rep = 0; rep < 4; rep++) {
            const int dv = d0 + (rep << 4);
            float4 t = *reinterpret_cast<const float4*>(qb + (size_t)cc * HD + dv);
            qs[(dv + 0) * TQ + cc] = t.x * 8.0f;
            qs[(dv + 1) * TQ + cc] = t.y * 8.0f;
            qs[(dv + 2) * TQ + cc] = t.z * 8.0f;
            qs[(dv + 3) * TQ + cc] = t.w * 8.0f;
        }
    }

    float acc[4][4] = {};
    float mrow[4] = {-1e30f, -1e30f, -1e30f, -1e30f};
    float lrow[4] = {0.f, 0.f, 0.f, 0.f};

    const float* kb0 = gk + ((size_t)(b * S) * H + h) * D;
    const float* vb0 = gv + ((size_t)(b * S) * H + h) * D;

    for (int k0 = 0; k0 < S; k0 += TK) {
        __syncthreads();   // previous tile finished reading ks/vs

        // ---- stage K (transposed) and V (natural) ----
        {
            const float* kb = kb0 + (size_t)k0 * HD;
            #pragma unroll
            for (int rep = 0; rep < 4; rep++) {
                const int dv = d0 + (rep << 4);
                float4 t = *reinterpret_cast<const float4*>(kb + (size_t)cc * HD + dv);
                ks[(dv + 0) * TK + cc] = t.x;
                ks[(dv + 1) * TK + cc] = t.y;
                ks[(dv + 2) * TK + cc] = t.z;
                ks[(dv + 3) * TK + cc] = t.w;
            }
            const float* vb = vb0 + (size_t)k0 * HD;
            #pragma unroll
            for (int rep = 0; rep < 4; rep++) {
                const int idx = tid + rep * NT;
                const int kk  = idx >> 4;
                const int dv  = (idx & 15) << 2;
                *reinterpret_cast<float4*>(&vs[kk * D + dv]) =
                    *reinterpret_cast<const float4*>(vb + (size_t)kk * HD + dv);
            }
        }
        __syncthreads();

        // ---- S = (Q*8) K^T : 16 FMA per d-step, q broadcast (1 wf) + k vec (2 wf) ----
        float sv[4][4] = {};
        #pragma unroll 8
        for (int d = 0; d < D; d++) {
            const float4 qv = *reinterpret_cast<const float4*>(&qs[d * TQ + (ty << 2)]);
            const float4 kv = *reinterpret_cast<const float4*>(&ks[d * TK + (tx << 2)]);
            const float qa[4] = {qv.x, qv.y, qv.z, qv.w};
            const float ka[4] = {kv.x, kv.y, kv.z, kv.w};
            #pragma unroll
            for (int i = 0; i < 4; i++)
                #pragma unroll
                for (int j = 0; j < 4; j++)
                    sv[i][j] = fmaf(qa[i], ka[j], sv[i][j]);
        }

        // ---- bias add, mask->0, online softmax, write P (padded) ----
        #pragma unroll
        for (int i = 0; i < 4; i++) {
            const int row = q0 + (ty << 2) + i;
            const float4 bv = *reinterpret_cast<const float4*>(
                gbias + ((size_t)bh * S + row) * S + k0 + (tx << 2));
            const int4 mv = *reinterpret_cast<const int4*>(
                gmask + ((size_t)b * S + row) * S + k0 + (tx << 2));
            sv[i][0] = mv.x ? 0.0f : sv[i][0] + bv.x;
            sv[i][1] = mv.y ? 0.0f : sv[i][1] + bv.y;
            sv[i][2] = mv.z ? 0.0f : sv[i][2] + bv.z;
            sv[i][3] = mv.w ? 0.0f : sv[i][3] + bv.w;

            float mx = fmaxf(fmaxf(sv[i][0], sv[i][1]), fmaxf(sv[i][2], sv[i][3]));
            #pragma unroll
            for (int off = 8; off; off >>= 1)
                mx = fmaxf(mx, __shfl_xor_sync(0xffffffffu, mx, off));
            const float mnew = fmaxf(mrow[i], mx);
            const float corr = __expf(mrow[i] - mnew);
            mrow[i] = mnew;

            float rs = 0.f;
            #pragma unroll
            for (int j = 0; j < 4; j++) {
                sv[i][j] = __expf(sv[i][j] - mnew);
                rs += sv[i][j];
            }
            #pragma unroll
            for (int off = 8; off; off >>= 1)
                rs += __shfl_xor_sync(0xffffffffu, rs, off);
            lrow[i] = lrow[i] * corr + rs;
            #pragma unroll
            for (int j = 0; j < 4; j++) acc[i][j] *= corr;

            *reinterpret_cast<float4*>(&ps[((ty << 2) + i) * PSS + (tx << 2)]) =
                make_float4(sv[i][0], sv[i][1], sv[i][2], sv[i][3]);
        }
        // P rows of this thread's micro-tile are produced/consumed within the
        // same warp (threads sharing ty are one half-warp) -> warp sync only.
        __syncwarp();

        // ---- O += P V : chunked by 4 kk; P rows via LDS.128 (conflict-free) ----
        #pragma unroll 4
        for (int kk4 = 0; kk4 < TK; kk4 += 4) {
            float p[4][4];
            #pragma unroll
            for (int i = 0; i < 4; i++) {
                const float4 pv = *reinterpret_cast<const float4*>(
                    &ps[((ty << 2) + i) * PSS + kk4]);
                p[i][0] = pv.x; p[i][1] = pv.y; p[i][2] = pv.z; p[i][3] = pv.w;
            }
            #pragma unroll
            for (int u = 0; u < 4; u++) {
                const float4 vv = *reinterpret_cast<const float4*>(
                    &vs[(kk4 + u) * D + (tx << 2)]);
                const float va[4] = {vv.x, vv.y, vv.z, vv.w};
                #pragma unroll
                for (int i = 0; i < 4; i++)
                    #pragma unroll
                    for (int j = 0; j < 4; j++)
                        acc[i][j] = fmaf(p[i][u], va[j], acc[i][j]);
            }
        }
    }

    // ---- epilogue: normalize and store [B,S,H,D] ----
    #pragma unroll
    for (int i = 0; i < 4; i++) {
        const float inv = 1.0f / lrow[i];
        const int row = q0 + (ty << 2) + i;
        const float4 o = make_float4(acc[i][0] * inv, acc[i][1] * inv,
                                     acc[i][2] * inv, acc[i][3] * inv);
        *reinterpret_cast<float4*>(
            gout + ((size_t)(b * S + row) * H + h) * D + (tx << 2)) = o;
    }
}

extern "C" void kernel_launch(void* const* d_in, const int* in_sizes, int n_in,
                              void* d_out, int out_size) {
    const float* q    = (const float*)d_in[0];
    const float* k    = (const float*)d_in[1];
    const float* v    = (const float*)d_in[2];
    const float* bias = (const float*)d_in[3];
    const int*   mask = (const int*)d_in[4];
    float* out = (float*)d_out;

    cudaFuncSetAttribute(attn_fp32_kernel,
                         cudaFuncAttributeMaxDynamicSharedMemorySize, SMEM_BYTES);
    dim3 grid(B * H, S / TQ);
    attn_fp32_kernel<<<grid, NT, SMEM_BYTES>>>(q, k, v, bias, mask, out);
}

// round 7
// speedup vs baseline: 2.4876x; 1.8389x over previous
#include <cuda_runtime.h>
#include <cuda_bf16.h>
#include <cstdint>

namespace {
constexpr int B  = 2;
constexpr int S  = 2048;
constexpr int H  = 16;
constexpr int D  = 64;
constexpr int TQ = 128;
constexpr int TK = 64;
constexpr int NT = 256;   // 8 warps
constexpr int HD = H * D;
// smem byte offsets: all arrays have 128-byte rows (64 bf16), SW128-swizzled
constexpr int QHI = 0;        // 128x64 bf16 = 16KB
constexpr int QLO = 16384;
constexpr int KHI = 32768;    // 64x64 bf16 = 8KB
constexpr int KLO = 40960;
constexpr int VHI = 49152;
constexpr int VLO = 57344;
constexpr int SMEM_BYTES = 65536;
}

__device__ __forceinline__ uint32_t swz(uint32_t off) { return off ^ ((off >> 3) & 0x70); }

__device__ __forceinline__ void ldsm4(uint32_t& r0, uint32_t& r1, uint32_t& r2, uint32_t& r3, uint32_t a) {
    asm volatile("ldmatrix.sync.aligned.m8n8.x4.shared.b16 {%0,%1,%2,%3},[%4];"
                 : "=r"(r0), "=r"(r1), "=r"(r2), "=r"(r3) : "r"(a));
}
__device__ __forceinline__ void ldsm4t(uint32_t& r0, uint32_t& r1, uint32_t& r2, uint32_t& r3, uint32_t a) {
    asm volatile("ldmatrix.sync.aligned.m8n8.x4.trans.shared.b16 {%0,%1,%2,%3},[%4];"
                 : "=r"(r0), "=r"(r1), "=r"(r2), "=r"(r3) : "r"(a));
}
__device__ __forceinline__ void mma16816(float c[4], uint32_t a0, uint32_t a1, uint32_t a2, uint32_t a3,
                                         uint32_t b0, uint32_t b1) {
    asm volatile("mma.sync.aligned.m16n8k16.row.col.f32.bf16.bf16.f32 "
                 "{%0,%1,%2,%3},{%4,%5,%6,%7},{%8,%9},{%0,%1,%2,%3};"
                 : "+f"(c[0]), "+f"(c[1]), "+f"(c[2]), "+f"(c[3])
                 : "r"(a0), "r"(a1), "r"(a2), "r"(a3), "r"(b0), "r"(b1));
}
__device__ __forceinline__ uint32_t pack_bf(float x, float y) {
    __nv_bfloat16 hx = __float2bfloat16_rn(x), hy = __float2bfloat16_rn(y);
    return (uint32_t)__bfloat16_as_ushort(hx) | ((uint32_t)__bfloat16_as_ushort(hy) << 16);
}
// split 4 floats into bf16 hi/lo 8-byte packs and store (swizzled)
__device__ __forceinline__ void sts_split4(char* sm, int hib, int lob, uint32_t off, float4 t) {
    const uint32_t so = swz(off);
    __nv_bfloat16 h0 = __float2bfloat16_rn(t.x), h1 = __float2bfloat16_rn(t.y);
    __nv_bfloat16 h2 = __float2bfloat16_rn(t.z), h3 = __float2bfloat16_rn(t.w);
    uint2 hv, lv;
    hv.x = (uint32_t)__bfloat16_as_ushort(h0) | ((uint32_t)__bfloat16_as_ushort(h1) << 16);
    hv.y = (uint32_t)__bfloat16_as_ushort(h2) | ((uint32_t)__bfloat16_as_ushort(h3) << 16);
    lv.x = pack_bf(t.x - __bfloat162float(h0), t.y - __bfloat162float(h1));
    lv.y = pack_bf(t.z - __bfloat162float(h2), t.w - __bfloat162float(h3));
    *reinterpret_cast<uint2*>(sm + hib + so) = hv;
    *reinterpret_cast<uint2*>(sm + lob + so) = lv;
}

__global__ void __launch_bounds__(NT, 1)
attn_mma_kernel(const float* __restrict__ gq, const float* __restrict__ gk,
                const float* __restrict__ gv, const float* __restrict__ gbias,
                const int*   __restrict__ gmask, float* __restrict__ gout)
{
    extern __shared__ char smem[];
    const uint32_t smu = (uint32_t)__cvta_generic_to_shared(smem);

    const int tid  = threadIdx.x;
    const int lane = tid & 31;
    const int w    = tid >> 5;      // warp 0..7, owns rows [16w, 16w+16)
    const int bh   = blockIdx.x;    // b*H + h (bias layout [B,H,S,S])
    const int b    = bh >> 4;
    const int h    = bh & 15;
    const int q0   = blockIdx.y * TQ;

    // per-lane ldmatrix geometry
    const int sub = lane >> 3, lr = lane & 7;
    const int a_row = 16 * w + lr + ((sub & 1) << 3);  // A tiles (Q / row-major)
    const int a_ca  = sub >> 1;
    const int b_ro  = lr + ((sub >> 1) << 3);          // B tiles, K (non-trans)
    const int b_ca  = sub & 1;
    const int v_ro  = lr + ((sub & 1) << 3);           // B tiles, V (trans)
    const int v_ca  = sub >> 1;

    // ---- stage Q (x8 pre-scale, bf16 hi/lo split, swizzled) ----
    {
        const float* qb = gq + ((size_t)(b * S + q0) * H + h) * D;
        #pragma unroll
        for (int r = 0; r < 8; r++) {
            const int l = r * NT + tid;
            const int row = l >> 4, c4 = l & 15;
            float4 t = *reinterpret_cast<const float4*>(qb + (size_t)row * HD + c4 * 4);
            t.x *= 8.0f; t.y *= 8.0f; t.z *= 8.0f; t.w *= 8.0f;
            sts_split4(smem, QHI, QLO, row * 128 + c4 * 8, t);
        }
    }
    __syncthreads();

    // ---- Q fragments resident in registers (hi + lo), 4 k-steps of k16 ----
    uint32_t qh[4][4], ql[4][4];
    #pragma unroll
    for (int ks = 0; ks < 4; ks++) {
        const uint32_t off = swz((uint32_t)(a_row * 128 + (2 * ks + a_ca) * 16));
        ldsm4(qh[ks][0], qh[ks][1], qh[ks][2], qh[ks][3], smu + QHI + off);
        ldsm4(ql[ks][0], ql[ks][1], ql[ks][2], ql[ks][3], smu + QLO + off);
    }

    float ofr[8][4];
    #pragma unroll
    for (int j = 0; j < 8; j++)
        #pragma unroll
        for (int e = 0; e < 4; e++) ofr[j][e] = 0.f;
    float mrow[2] = {-1e30f, -1e30f};
    float lrow[2] = {0.f, 0.f};

    const float* kb0 = gk + ((size_t)(b * S) * H + h) * D;
    const float* vb0 = gv + ((size_t)(b * S) * H + h) * D;

    // K/V gmem prefetch registers (tile i+1 loaded during tile i compute)
    float4 kreg[4], vreg[4];
    #pragma unroll
    for (int r = 0; r < 4; r++) {
        const int l = r * NT + tid;
        const int row = l >> 4, c4 = l & 15;
        kreg[r] = *reinterpret_cast<const float4*>(kb0 + (size_t)row * HD + c4 * 4);
        vreg[r] = *reinterpret_cast<const float4*>(vb0 + (size_t)row * HD + c4 * 4);
    }

    const int rr0 = q0 + 16 * w + (lane >> 2);   // global row for p=0 (p=1: +8)

    for (int it = 0; it < S / TK; it++) {
        const int k0 = it * TK;
        __syncthreads();   // previous tile's ldmatrix reads done

        // ---- store staged K/V (bf16 hi/lo split) ----
        #pragma unroll
        for (int r = 0; r < 4; r++) {
            const int l = r * NT + tid;
            const int row = l >> 4, c4 = l & 15;
            sts_split4(smem, KHI, KLO, row * 128 + c4 * 8, kreg[r]);
            sts_split4(smem, VHI, VLO, row * 128 + c4 * 8, vreg[r]);
        }
        __syncthreads();

        // prefetch next K/V tile into registers (hidden under MMA below)
        if (it + 1 < S / TK) {
            const float* kb = kb0 + (size_t)(k0 + TK) * HD;
            const float* vb = vb0 + (size_t)(k0 + TK) * HD;
            #pragma unroll
            for (int r = 0; r < 4; r++) {
                const int l = r * NT + tid;
                const int row = l >> 4, c4 = l & 15;
                kreg[r] = *reinterpret_cast<const float4*>(kb + (size_t)row * HD + c4 * 4);
                vreg[r] = *reinterpret_cast<const float4*>(vb + (size_t)row * HD + c4 * 4);
            }
        }

        // issue bias + mask loads (consumed after QK MMAs)
        float2 bfr[16];
        int2   mfr[16];
        #pragma unroll
        for (int j = 0; j < 8; j++)
            #pragma unroll
            for (int p = 0; p < 2; p++) {
                const int row = rr0 + 8 * p;
                const int col = k0 + 8 * j + (lane & 3) * 2;
                bfr[j * 2 + p] = *reinterpret_cast<const float2*>(
                    gbias + ((size_t)bh * S + row) * S + col);
                mfr[j * 2 + p] = *reinterpret_cast<const int2*>(
                    gmask + ((size_t)b * S + row) * S + col);
            }

        // ---- S = (Q*8) K^T : 3-term bf16 split MMA ----
        float sfr[8][4];
        #pragma unroll
        for (int j = 0; j < 8; j++)
            #pragma unroll
            for (int e = 0; e < 4; e++) sfr[j][e] = 0.f;

        #pragma unroll
        for (int ks = 0; ks < 4; ks++) {
            #pragma unroll
            for (int i = 0; i < 4; i++) {
                const uint32_t off = swz((uint32_t)((16 * i + b_ro) * 128 + (2 * ks + b_ca) * 16));
                uint32_t kh0, kh1, kh2, kh3, kl0, kl1, kl2, kl3;
                ldsm4(kh0, kh1, kh2, kh3, smu + KHI + off);
                ldsm4(kl0, kl1, kl2, kl3, smu + KLO + off);
                mma16816(sfr[2 * i],     qh[ks][0], qh[ks][1], qh[ks][2], qh[ks][3], kh0, kh1);
                mma16816(sfr[2 * i],     qh[ks][0], qh[ks][1], qh[ks][2], qh[ks][3], kl0, kl1);
                mma16816(sfr[2 * i],     ql[ks][0], ql[ks][1], ql[ks][2], ql[ks][3], kh0, kh1);
                mma16816(sfr[2 * i + 1], qh[ks][0], qh[ks][1], qh[ks][2], qh[ks][3], kh2, kh3);
                mma16816(sfr[2 * i + 1], qh[ks][0], qh[ks][1], qh[ks][2], qh[ks][3], kl2, kl3);
                mma16816(sfr[2 * i + 1], ql[ks][0], ql[ks][1], ql[ks][2], ql[ks][3], kh2, kh3);
            }
        }

        // ---- bias, mask->0, online softmax (rows are warp-local; 4 lanes/row) ----
        #pragma unroll
        for (int p = 0; p < 2; p++) {
            float mx = -1e30f;
            #pragma unroll
            for (int j = 0; j < 8; j++) {
                const float2 bv = bfr[j * 2 + p];
                const int2   mv = mfr[j * 2 + p];
                float v0 = mv.x ? 0.0f : sfr[j][2 * p]     + bv.x;
                float v1 = mv.y ? 0.0f : sfr[j][2 * p + 1] + bv.y;
                sfr[j][2 * p] = v0; sfr[j][2 * p + 1] = v1;
                mx = fmaxf(mx, fmaxf(v0, v1));
            }
            mx = fmaxf(mx, __shfl_xor_sync(0xffffffffu, mx, 1));
            mx = fmaxf(mx, __shfl_xor_sync(0xffffffffu, mx, 2));
            const float mnew = fmaxf(mrow[p], mx);
            const float corr = __expf(mrow[p] - mnew);
            mrow[p] = mnew;

            float rs = 0.f;
            #pragma unroll
            for (int j = 0; j < 8; j++) {
                const float e0 = __expf(sfr[j][2 * p]     - mnew);
                const float e1 = __expf(sfr[j][2 * p + 1] - mnew);
                sfr[j][2 * p] = e0; sfr[j][2 * p + 1] = e1;
                rs += e0 + e1;
            }
            rs += __shfl_xor_sync(0xffffffffu, rs, 1);
            rs += __shfl_xor_sync(0xffffffffu, rs, 2);
            lrow[p] = lrow[p] * corr + rs;
            #pragma unroll
            for (int j = 0; j < 8; j++) {
                ofr[j][2 * p] *= corr; ofr[j][2 * p + 1] *= corr;
            }
        }

        // ---- P fragments (registers only): C-frag pairs == A-frag of k16 ----
        uint32_t ph[4][4], pl[4][4];
        #pragma unroll
        for (int ks = 0; ks < 4; ks++) {
            #pragma unroll
            for (int half = 0; half < 2; half++) {      // c-frags 2ks (a0,a1) and 2ks+1 (a2,a3)
                const int j = 2 * ks + half;
                #pragma unroll
                for (int p = 0; p < 2; p++) {
                    const float x = sfr[j][2 * p], y = sfr[j][2 * p + 1];
                    const __nv_bfloat16 hx = __float2bfloat16_rn(x), hy = __float2bfloat16_rn(y);
                    ph[ks][half * 2 + p] =
                        (uint32_t)__bfloat16_as_ushort(hx) | ((uint32_t)__bfloat16_as_ushort(hy) << 16);
                    pl[ks][half * 2 + p] =
                        pack_bf(x - __bfloat162float(hx), y - __bfloat162float(hy));
                }
            }
        }

        // ---- O += P V : 3-term split, V via ldmatrix.trans ----
        #pragma unroll
        for (int ks = 0; ks < 4; ks++) {
            #pragma unroll
            for (int i = 0; i < 4; i++) {
                const uint32_t off = swz((uint32_t)((16 * ks + v_ro) * 128 + (2 * i + v_ca) * 16));
                uint32_t vh0, vh1, vh2, vh3, vl0, vl1, vl2, vl3;
                ldsm4t(vh0, vh1, vh2, vh3, smu + VHI + off);
                ldsm4t(vl0, vl1, vl2, vl3, smu + VLO + off);
                mma16816(ofr[2 * i],     ph[ks][0], ph[ks][1], ph[ks][2], ph[ks][3], vh0, vh1);
                mma16816(ofr[2 * i],     ph[ks][0], ph[ks][1], ph[ks][2], ph[ks][3], vl0, vl1);
                mma16816(ofr[2 * i],     pl[ks][0], pl[ks][1], pl[ks][2], pl[ks][3], vh0, vh1);
                mma16816(ofr[2 * i + 1], ph[ks][0], ph[ks][1], ph[ks][2], ph[ks][3], vh2, vh3);
                mma16816(ofr[2 * i + 1], ph[ks][0], ph[ks][1], ph[ks][2], ph[ks][3], vl2, vl3);
                mma16816(ofr[2 * i + 1], pl[ks][0], pl[ks][1], pl[ks][2], pl[ks][3], vh2, vh3);
            }
        }
    }

    // ---- epilogue: normalize, store [B,S,H,D] ----
    const float inv0 = 1.0f / lrow[0];
    const float inv1 = 1.0f / lrow[1];
    #pragma unroll
    for (int j = 0; j < 8; j++) {
        const int d = 8 * j + (lane & 3) * 2;
        float2 w0 = make_float2(ofr[j][0] * inv0, ofr[j][1] * inv0);
        float2 w1 = make_float2(ofr[j][2] * inv1, ofr[j][3] * inv1);
        *reinterpret_cast<float2*>(gout + ((size_t)(b * S + rr0)     * H + h) * D + d) = w0;
        *reinterpret_cast<float2*>(gout + ((size_t)(b * S + rr0 + 8) * H + h) * D + d) = w1;
    }
}

extern "C" void kernel_launch(void* const* d_in, const int* in_sizes, int n_in,
                              void* d_out, int out_size) {
    const float* q    = (const float*)d_in[0];
    const float* k    = (const float*)d_in[1];
    const float* v    = (const float*)d_in[2];
    const float* bias = (const float*)d_in[3];
    const int*   mask = (const int*)d_in[4];
    float* out = (float*)d_out;

    cudaFuncSetAttribute(attn_mma_kernel,
                         cudaFuncAttributeMaxDynamicSharedMemorySize, SMEM_BYTES);
    dim3 grid(B * H, S / TQ);
    attn_mma_kernel<<<grid, NT, SMEM_BYTES>>>(q, k, v, bias, mask, out);
}

// round 8
// speedup vs baseline: 2.6429x; 1.0624x over previous
#include <cuda_runtime.h>
#include <cuda_bf16.h>
#include <cstdint>

namespace {
constexpr int B  = 2;
constexpr int S  = 2048;
constexpr int H  = 16;
constexpr int D  = 64;
constexpr int TQ = 64;
constexpr int TK = 64;
constexpr int NT = 128;   // 4 warps
constexpr int HD = H * D;
constexpr int NTILES = S / TK;
// smem layout (64KB): fp32 staging + split-bf16 tiles. Q aliases KHI/KLO in prologue.
constexpr int STAGE_K = 0;        // 64x64 fp32 = 16KB
constexpr int STAGE_V = 16384;    // 16KB
constexpr int KHI = 32768;        // 64x64 bf16 = 8KB  (prologue: QHI)
constexpr int KLO = 40960;        //                    (prologue: QLO)
constexpr int VHI = 49152;
constexpr int VLO = 57344;
constexpr int SMEM_BYTES = 65536;
}

__device__ __forceinline__ uint32_t swz(uint32_t off) { return off ^ ((off >> 3) & 0x70); }

__device__ __forceinline__ void cpasync16(uint32_t dst, const void* src) {
    asm volatile("cp.async.cg.shared.global [%0], [%1], 16;" :: "r"(dst), "l"(src));
}
__device__ __forceinline__ void ldsm4(uint32_t& r0, uint32_t& r1, uint32_t& r2, uint32_t& r3, uint32_t a) {
    asm volatile("ldmatrix.sync.aligned.m8n8.x4.shared.b16 {%0,%1,%2,%3},[%4];"
                 : "=r"(r0), "=r"(r1), "=r"(r2), "=r"(r3) : "r"(a));
}
__device__ __forceinline__ void ldsm4t(uint32_t& r0, uint32_t& r1, uint32_t& r2, uint32_t& r3, uint32_t a) {
    asm volatile("ldmatrix.sync.aligned.m8n8.x4.trans.shared.b16 {%0,%1,%2,%3},[%4];"
                 : "=r"(r0), "=r"(r1), "=r"(r2), "=r"(r3) : "r"(a));
}
__device__ __forceinline__ void mma16816(float c[4], uint32_t a0, uint32_t a1, uint32_t a2, uint32_t a3,
                                         uint32_t b0, uint32_t b1) {
    asm volatile("mma.sync.aligned.m16n8k16.row.col.f32.bf16.bf16.f32 "
                 "{%0,%1,%2,%3},{%4,%5,%6,%7},{%8,%9},{%0,%1,%2,%3};"
                 : "+f"(c[0]), "+f"(c[1]), "+f"(c[2]), "+f"(c[3])
                 : "r"(a0), "r"(a1), "r"(a2), "r"(a3), "r"(b0), "r"(b1));
}
__device__ __forceinline__ uint32_t pack_bf(float x, float y) {
    __nv_bfloat16 hx = __float2bfloat16_rn(x), hy = __float2bfloat16_rn(y);
    return (uint32_t)__bfloat16_as_ushort(hx) | ((uint32_t)__bfloat16_as_ushort(hy) << 16);
}
__device__ __forceinline__ void sts_split4(char* sm, int hib, int lob, uint32_t off, float4 t) {
    const uint32_t so = swz(off);
    __nv_bfloat16 h0 = __float2bfloat16_rn(t.x), h1 = __float2bfloat16_rn(t.y);
    __nv_bfloat16 h2 = __float2bfloat16_rn(t.z), h3 = __float2bfloat16_rn(t.w);
    uint2 hv, lv;
    hv.x = (uint32_t)__bfloat16_as_ushort(h0) | ((uint32_t)__bfloat16_as_ushort(h1) << 16);
    hv.y = (uint32_t)__bfloat16_as_ushort(h2) | ((uint32_t)__bfloat16_as_ushort(h3) << 16);
    lv.x = pack_bf(t.x - __bfloat162float(h0), t.y - __bfloat162float(h1));
    lv.y = pack_bf(t.z - __bfloat162float(h2), t.w - __bfloat162float(h3));
    *reinterpret_cast<uint2*>(sm + hib + so) = hv;
    *reinterpret_cast<uint2*>(sm + lob + so) = lv;
}

__global__ void __launch_bounds__(NT, 3)
attn_mma_kernel(const float* __restrict__ gq, const float* __restrict__ gk,
                const float* __restrict__ gv, const float* __restrict__ gbias,
                const int*   __restrict__ gmask, float* __restrict__ gout)
{
    extern __shared__ char smem[];
    const uint32_t smu = (uint32_t)__cvta_generic_to_shared(smem);

    const int tid  = threadIdx.x;
    const int lane = tid & 31;
    const int w    = tid >> 5;      // warp 0..3, owns rows [16w, 16w+16)
    const int bh   = blockIdx.x;    // b*H + h
    const int b    = bh >> 4;
    const int h    = bh & 15;
    const int q0   = blockIdx.y * TQ;

    // ldmatrix lane geometry
    const int sub = lane >> 3, lr = lane & 7;
    const int a_row = 16 * w + lr + ((sub & 1) << 3);
    const int a_ca  = sub >> 1;
    const int b_ro  = lr + ((sub >> 1) << 3);
    const int b_ca  = sub & 1;
    const int v_ro  = lr + ((sub & 1) << 3);
    const int v_ca  = sub >> 1;

    const float* kb0 = gk + ((size_t)(b * S) * H + h) * D;
    const float* vb0 = gv + ((size_t)(b * S) * H + h) * D;

    // ---- issue cp.async for K0/V0 immediately ----
    #pragma unroll
    for (int r = 0; r < 8; r++) {
        const int idx = r * NT + tid;
        const int row = idx >> 4, c16 = idx & 15;
        cpasync16((uint32_t)(smu + STAGE_K + row * 256 + c16 * 16), kb0 + (size_t)row * HD + c16 * 4);
        cpasync16((uint32_t)(smu + STAGE_V + row * 256 + c16 * 16), vb0 + (size_t)row * HD + c16 * 4);
    }
    asm volatile("cp.async.commit_group;");

    // ---- stage Q (x8, split) into the KHI/KLO area, take fragments ----
    {
        const float* qb = gq + ((size_t)(b * S + q0) * H + h) * D;
        #pragma unroll
        for (int r = 0; r < 8; r++) {
            const int idx = r * NT + tid;
            const int row = idx >> 4, c16 = idx & 15;
            float4 t = *reinterpret_cast<const float4*>(qb + (size_t)row * HD + c16 * 4);
            t.x *= 8.0f; t.y *= 8.0f; t.z *= 8.0f; t.w *= 8.0f;
            sts_split4(smem, KHI, KLO, row * 128 + c16 * 8, t);
        }
    }
    __syncthreads();

    uint32_t qh[4][4], ql[4][4];
    #pragma unroll
    for (int ks = 0; ks < 4; ks++) {
        const uint32_t off = swz((uint32_t)(a_row * 128 + (2 * ks + a_ca) * 16));
        ldsm4(qh[ks][0], qh[ks][1], qh[ks][2], qh[ks][3], smu + KHI + off);
        ldsm4(ql[ks][0], ql[ks][1], ql[ks][2], ql[ks][3], smu + KLO + off);
    }
    asm volatile("cp.async.wait_group 0;");
    __syncthreads();   // Q reads done; staging K0/V0 ready

    float ofr[8][4];
    #pragma unroll
    for (int j = 0; j < 8; j++)
        #pragma unroll
        for (int e = 0; e < 4; e++) ofr[j][e] = 0.f;
    float mrow[2] = {-1e30f, -1e30f};
    float lrow[2] = {0.f, 0.f};

    const int rr0 = q0 + 16 * w + (lane >> 2);

    for (int it = 0; it < NTILES; it++) {
        const int k0 = it * TK;

        // ---- convert staging fp32 -> split bf16 K/V ----
        #pragma unroll
        for (int r = 0; r < 8; r++) {
            const int idx = r * NT + tid;
            const int row = idx >> 4, c16 = idx & 15;
            float4 kt = *reinterpret_cast<const float4*>(smem + STAGE_K + row * 256 + c16 * 16);
            float4 vt = *reinterpret_cast<const float4*>(smem + STAGE_V + row * 256 + c16 * 16);
            sts_split4(smem, KHI, KLO, row * 128 + c16 * 8, kt);
            sts_split4(smem, VHI, VLO, row * 128 + c16 * 8, vt);
        }
        __syncthreads();

        // ---- prefetch next tile via cp.async (hidden under this tile's MMAs) ----
        if (it + 1 < NTILES) {
            const float* kb = kb0 + (size_t)(k0 + TK) * HD;
            const float* vb = vb0 + (size_t)(k0 + TK) * HD;
            #pragma unroll
            for (int r = 0; r < 8; r++) {
                const int idx = r * NT + tid;
                const int row = idx >> 4, c16 = idx & 15;
                cpasync16((uint32_t)(smu + STAGE_K + row * 256 + c16 * 16), kb + (size_t)row * HD + c16 * 4);
                cpasync16((uint32_t)(smu + STAGE_V + row * 256 + c16 * 16), vb + (size_t)row * HD + c16 * 4);
            }
        }
        asm volatile("cp.async.commit_group;");

        // ---- two 32-key halves ----
        #pragma unroll
        for (int hf = 0; hf < 2; hf++) {
            // bias + mask loads for this half (consumed after QK MMAs)
            float2 bfr[4][2];
            int2   mfr[4][2];
            #pragma unroll
            for (int j = 0; j < 4; j++)
                #pragma unroll
                for (int p = 0; p < 2; p++) {
                    const int row = rr0 + 8 * p;
                    const int col = k0 + 32 * hf + 8 * j + (lane & 3) * 2;
                    bfr[j][p] = *reinterpret_cast<const float2*>(
                        gbias + ((size_t)bh * S + row) * S + col);
                    mfr[j][p] = *reinterpret_cast<const int2*>(
                        gmask + ((size_t)b * S + row) * S + col);
                }

            // QK: 3-term split over 2 key blocks (32 keys)
            float sfr[4][4];
            #pragma unroll
            for (int j = 0; j < 4; j++)
                #pragma unroll
                for (int e = 0; e < 4; e++) sfr[j][e] = 0.f;

            #pragma unroll
            for (int ks = 0; ks < 4; ks++) {
                #pragma unroll
                for (int ii = 0; ii < 2; ii++) {
                    const int i = 2 * hf + ii;
                    const uint32_t off = swz((uint32_t)((16 * i + b_ro) * 128 + (2 * ks + b_ca) * 16));
                    uint32_t kh0, kh1, kh2, kh3, kl0, kl1, kl2, kl3;
                    ldsm4(kh0, kh1, kh2, kh3, smu + KHI + off);
                    ldsm4(kl0, kl1, kl2, kl3, smu + KLO + off);
                    mma16816(sfr[2 * ii],     qh[ks][0], qh[ks][1], qh[ks][2], qh[ks][3], kh0, kh1);
                    mma16816(sfr[2 * ii],     qh[ks][0], qh[ks][1], qh[ks][2], qh[ks][3], kl0, kl1);
                    mma16816(sfr[2 * ii],     ql[ks][0], ql[ks][1], ql[ks][2], ql[ks][3], kh0, kh1);
                    mma16816(sfr[2 * ii + 1], qh[ks][0], qh[ks][1], qh[ks][2], qh[ks][3], kh2, kh3);
                    mma16816(sfr[2 * ii + 1], qh[ks][0], qh[ks][1], qh[ks][2], qh[ks][3], kl2, kl3);
                    mma16816(sfr[2 * ii + 1], ql[ks][0], ql[ks][1], ql[ks][2], ql[ks][3], kh2, kh3);
                }
            }

            // bias, mask->0, online softmax
            #pragma unroll
            for (int p = 0; p < 2; p++) {
                float mx = -1e30f;
                #pragma unroll
                for (int j = 0; j < 4; j++) {
                    const float2 bv = bfr[j][p];
                    const int2   mv = mfr[j][p];
                    float v0 = mv.x ? 0.0f : sfr[j][2 * p]     + bv.x;
                    float v1 = mv.y ? 0.0f : sfr[j][2 * p + 1] + bv.y;
                    sfr[j][2 * p] = v0; sfr[j][2 * p + 1] = v1;
                    mx = fmaxf(mx, fmaxf(v0, v1));
                }
                mx = fmaxf(mx, __shfl_xor_sync(0xffffffffu, mx, 1));
                mx = fmaxf(mx, __shfl_xor_sync(0xffffffffu, mx, 2));
                const float mnew = fmaxf(mrow[p], mx);
                const float corr = __expf(mrow[p] - mnew);
                mrow[p] = mnew;

                float rs = 0.f;
                #pragma unroll
                for (int j = 0; j < 4; j++) {
                    const float e0 = __expf(sfr[j][2 * p]     - mnew);
                    const float e1 = __expf(sfr[j][2 * p + 1] - mnew);
                    sfr[j][2 * p] = e0; sfr[j][2 * p + 1] = e1;
                    rs += e0 + e1;
                }
                rs += __shfl_xor_sync(0xffffffffu, rs, 1);
                rs += __shfl_xor_sync(0xffffffffu, rs, 2);
                lrow[p] = lrow[p] * corr + rs;
                #pragma unroll
                for (int j = 0; j < 8; j++) {
                    ofr[j][2 * p] *= corr; ofr[j][2 * p + 1] *= corr;
                }
            }

            // P fragments for this half (2 k16 steps over these 32 keys)
            uint32_t ph[2][4], pl[2][4];
            #pragma unroll
            for (int ksp = 0; ksp < 2; ksp++) {
                #pragma unroll
                for (int half = 0; half < 2; half++) {
                    const int j = 2 * ksp + half;
                    #pragma unroll
                    for (int p = 0; p < 2; p++) {
                        const float x = sfr[j][2 * p], y = sfr[j][2 * p + 1];
                        const __nv_bfloat16 hx = __float2bfloat16_rn(x), hy = __float2bfloat16_rn(y);
                        ph[ksp][half * 2 + p] =
                            (uint32_t)__bfloat16_as_ushort(hx) | ((uint32_t)__bfloat16_as_ushort(hy) << 16);
                        pl[ksp][half * 2 + p] =
                            pack_bf(x - __bfloat162float(hx), y - __bfloat162float(hy));
                    }
                }
            }

            // O += P V for this half
            #pragma unroll
            for (int ksp = 0; ksp < 2; ksp++) {
                const int kb16 = 2 * hf + ksp;   // key block of 16
                #pragma unroll
                for (int i = 0; i < 4; i++) {
                    const uint32_t off = swz((uint32_t)((16 * kb16 + v_ro) * 128 + (2 * i + v_ca) * 16));
                    uint32_t vh0, vh1, vh2, vh3, vl0, vl1, vl2, vl3;
                    ldsm4t(vh0, vh1, vh2, vh3, smu + VHI + off);
                    ldsm4t(vl0, vl1, vl2, vl3, smu + VLO + off);
                    mma16816(ofr[2 * i],     ph[ksp][0], ph[ksp][1], ph[ksp][2], ph[ksp][3], vh0, vh1);
                    mma16816(ofr[2 * i],     ph[ksp][0], ph[ksp][1], ph[ksp][2], ph[ksp][3], vl0, vl1);
                    mma16816(ofr[2 * i],     pl[ksp][0], pl[ksp][1], pl[ksp][2], pl[ksp][3], vh0, vh1);
                    mma16816(ofr[2 * i + 1], ph[ksp][0], ph[ksp][1], ph[ksp][2], ph[ksp][3], vh2, vh3);
                    mma16816(ofr[2 * i + 1], ph[ksp][0], ph[ksp][1], ph[ksp][2], ph[ksp][3], vl2, vl3);
                    mma16816(ofr[2 * i + 1], pl[ksp][0], pl[ksp][1], pl[ksp][2], pl[ksp][3], vh2, vh3);
                }
            }
        }

        asm volatile("cp.async.wait_group 0;");
        __syncthreads();   // all ldmatrix reads done; staging for next tile arrived
    }

    // ---- epilogue: normalize, store [B,S,H,D] ----
    const float inv0 = 1.0f / lrow[0];
    const float inv1 = 1.0f / lrow[1];
    #pragma unroll
    for (int j = 0; j < 8; j++) {
        const int d = 8 * j + (lane & 3) * 2;
        float2 w0 = make_float2(ofr[j][0] * inv0, ofr[j][1] * inv0);
        float2 w1 = make_float2(ofr[j][2] * inv1, ofr[j][3] * inv1);
        *reinterpret_cast<float2*>(gout + ((size_t)(b * S + rr0)     * H + h) * D + d) = w0;
        *reinterpret_cast<float2*>(gout + ((size_t)(b * S + rr0 + 8) * H + h) * D + d) = w1;
    }
}

extern "C" void kernel_launch(void* const* d_in, const int* in_sizes, int n_in,
                              void* d_out, int out_size) {
    const float* q    = (const float*)d_in[0];
    const float* k    = (const float*)d_in[1];
    const float* v    = (const float*)d_in[2];
    const float* bias = (const float*)d_in[3];
    const int*   mask = (const int*)d_in[4];
    float* out = (float*)d_out;

    cudaFuncSetAttribute(attn_mma_kernel,
                         cudaFuncAttributeMaxDynamicSharedMemorySize, SMEM_BYTES);
    dim3 grid(B * H, S / TQ);
    attn_mma_kernel<<<grid, NT, SMEM_BYTES>>>(q, k, v, bias, mask, out);
}

// round 9
// speedup vs baseline: 3.0615x; 1.1584x over previous
#include <cuda_runtime.h>
#include <cuda_bf16.h>
#include <cstdint>

namespace {
constexpr int B  = 2;
constexpr int S  = 2048;
constexpr int H  = 16;
constexpr int D  = 64;
constexpr int TQ = 64;
constexpr int TK = 64;
constexpr int NT = 128;   // 4 warps
constexpr int HD = H * D;
constexpr int NTILES = S / TK;     // 32
constexpr int TILE_BYTES = 64 * 128;        // 8KB per split component
// smem: two 32KB buffers; within a buffer: KHI 0, KLO 8K, VHI 16K, VLO 24K
constexpr int BUF = 32768;
constexpr int SMEM_BYTES = 2 * BUF;         // 64KB
}

// Pre-split, pre-swizzled K/V tiles: [bh][tile] blocks of 8KB each.
__device__ __align__(16) unsigned char gKH[(size_t)B * H * NTILES * TILE_BYTES];
__device__ __align__(16) unsigned char gKL[(size_t)B * H * NTILES * TILE_BYTES];
__device__ __align__(16) unsigned char gVH[(size_t)B * H * NTILES * TILE_BYTES];
__device__ __align__(16) unsigned char gVL[(size_t)B * H * NTILES * TILE_BYTES];

__device__ __forceinline__ uint32_t swz(uint32_t off) { return off ^ ((off >> 3) & 0x70); }

__device__ __forceinline__ void cpasync16(uint32_t dst, const void* src) {
    asm volatile("cp.async.cg.shared.global [%0], [%1], 16;" :: "r"(dst), "l"(src));
}
__device__ __forceinline__ void ldsm4(uint32_t& r0, uint32_t& r1, uint32_t& r2, uint32_t& r3, uint32_t a) {
    asm volatile("ldmatrix.sync.aligned.m8n8.x4.shared.b16 {%0,%1,%2,%3},[%4];"
                 : "=r"(r0), "=r"(r1), "=r"(r2), "=r"(r3) : "r"(a));
}
__device__ __forceinline__ void ldsm4t(uint32_t& r0, uint32_t& r1, uint32_t& r2, uint32_t& r3, uint32_t a) {
    asm volatile("ldmatrix.sync.aligned.m8n8.x4.trans.shared.b16 {%0,%1,%2,%3},[%4];"
                 : "=r"(r0), "=r"(r1), "=r"(r2), "=r"(r3) : "r"(a));
}
__device__ __forceinline__ void mma16816(float c[4], uint32_t a0, uint32_t a1, uint32_t a2, uint32_t a3,
                                         uint32_t b0, uint32_t b1) {
    asm volatile("mma.sync.aligned.m16n8k16.row.col.f32.bf16.bf16.f32 "
                 "{%0,%1,%2,%3},{%4,%5,%6,%7},{%8,%9},{%0,%1,%2,%3};"
                 : "+f"(c[0]), "+f"(c[1]), "+f"(c[2]), "+f"(c[3])
                 : "r"(a0), "r"(a1), "r"(a2), "r"(a3), "r"(b0), "r"(b1));
}
__device__ __forceinline__ uint32_t pack_bf(float x, float y) {
    __nv_bfloat16 hx = __float2bfloat16_rn(x), hy = __float2bfloat16_rn(y);
    return (uint32_t)__bfloat16_as_ushort(hx) | ((uint32_t)__bfloat16_as_ushort(hy) << 16);
}
__device__ __forceinline__ void split4(float4 t, uint2& hv, uint2& lv) {
    __nv_bfloat16 h0 = __float2bfloat16_rn(t.x), h1 = __float2bfloat16_rn(t.y);
    __nv_bfloat16 h2 = __float2bfloat16_rn(t.z), h3 = __float2bfloat16_rn(t.w);
    hv.x = (uint32_t)__bfloat16_as_ushort(h0) | ((uint32_t)__bfloat16_as_ushort(h1) << 16);
    hv.y = (uint32_t)__bfloat16_as_ushort(h2) | ((uint32_t)__bfloat16_as_ushort(h3) << 16);
    lv.x = pack_bf(t.x - __bfloat162float(h0), t.y - __bfloat162float(h1));
    lv.y = pack_bf(t.z - __bfloat162float(h2), t.w - __bfloat162float(h3));
}

// ---- prepass: K/V fp32 [B,S,H,D] -> split bf16, swizzled 8KB tile blocks ----
__global__ void __launch_bounds__(256)
split_kv_kernel(const float* __restrict__ gk, const float* __restrict__ gv)
{
    const int idx = blockIdx.x * 256 + threadIdx.x;   // [0, B*H*S*16)
    const int c16 = idx & 15;
    const int s   = (idx >> 4) & (S - 1);
    const int bh  = idx >> 15;
    const int b = bh >> 4, h = bh & 15;

    const size_t gsrc = ((size_t)(b * S + s) * H + h) * D + c16 * 4;
    const float4 kt = *reinterpret_cast<const float4*>(gk + gsrc);
    const float4 vt = *reinterpret_cast<const float4*>(gv + gsrc);

    const size_t base = ((size_t)(bh * NTILES + (s >> 6)) << 13)
                      + swz((uint32_t)((s & 63) * 128 + c16 * 8));
    uint2 hv, lv;
    split4(kt, hv, lv);
    *reinterpret_cast<uint2*>(gKH + base) = hv;
    *reinterpret_cast<uint2*>(gKL + base) = lv;
    split4(vt, hv, lv);
    *reinterpret_cast<uint2*>(gVH + base) = hv;
    *reinterpret_cast<uint2*>(gVL + base) = lv;
}

__global__ void __launch_bounds__(NT, 3)
attn_mma_kernel(const float* __restrict__ gq, const float* __restrict__ gbias,
                const int*   __restrict__ gmask, float* __restrict__ gout)
{
    extern __shared__ char smem[];
    const uint32_t smu = (uint32_t)__cvta_generic_to_shared(smem);

    const int tid  = threadIdx.x;
    const int lane = tid & 31;
    const int w    = tid >> 5;
    const int bh   = blockIdx.x;
    const int b    = bh >> 4;
    const int h    = bh & 15;
    const int q0   = blockIdx.y * TQ;

    // ldmatrix lane geometry
    const int sub = lane >> 3, lr = lane & 7;
    const int a_row = 16 * w + lr + ((sub & 1) << 3);
    const int a_ca  = sub >> 1;
    const int b_ro  = lr + ((sub >> 1) << 3);
    const int b_ca  = sub & 1;
    const int v_ro  = lr + ((sub & 1) << 3);
    const int v_ca  = sub >> 1;

    const size_t tile_base0 = (size_t)(bh * NTILES) << 13;

    // issue tile0 copy into buf0 immediately (overlaps Q staging below)
    {
        const uint32_t dst = smu;   // buf0
        #pragma unroll
        for (int r = 0; r < 4; r++) {
            const int off = r * 2048 + tid * 16;
            cpasync16(dst + off,         gKH + tile_base0 + off);
            cpasync16(dst + 8192 + off,  gKL + tile_base0 + off);
            cpasync16(dst + 16384 + off, gVH + tile_base0 + off);
            cpasync16(dst + 24576 + off, gVL + tile_base0 + off);
        }
    }
    asm volatile("cp.async.commit_group;");

    // ---- stage Q (x8, split) into buf1, take register fragments ----
    {
        const float* qb = gq + ((size_t)(b * S + q0) * H + h) * D;
        #pragma unroll
        for (int r = 0; r < 8; r++) {
            const int idx = r * NT + tid;
            const int row = idx >> 4, c16 = idx & 15;
            float4 t = *reinterpret_cast<const float4*>(qb + (size_t)row * HD + c16 * 4);
            t.x *= 8.0f; t.y *= 8.0f; t.z *= 8.0f; t.w *= 8.0f;
            uint2 hv, lv;
            split4(t, hv, lv);
            const uint32_t so = swz((uint32_t)(row * 128 + c16 * 8));
            *reinterpret_cast<uint2*>(smem + BUF + so)        = hv;
            *reinterpret_cast<uint2*>(smem + BUF + 8192 + so) = lv;
        }
    }
    __syncthreads();

    uint32_t qh[4][4], ql[4][4];
    #pragma unroll
    for (int ks = 0; ks < 4; ks++) {
        const uint32_t off = swz((uint32_t)(a_row * 128 + (2 * ks + a_ca) * 16));
        ldsm4(qh[ks][0], qh[ks][1], qh[ks][2], qh[ks][3], smu + BUF + off);
        ldsm4(ql[ks][0], ql[ks][1], ql[ks][2], ql[ks][3], smu + BUF + 8192 + off);
    }
    __syncthreads();   // Q reads done; buf1 reusable

    // issue tile1 copy into buf1
    {
        const size_t tb = tile_base0 + TILE_BYTES;
        const uint32_t dst = smu + BUF;
        #pragma unroll
        for (int r = 0; r < 4; r++) {
            const int off = r * 2048 + tid * 16;
            cpasync16(dst + off,         gKH + tb + off);
            cpasync16(dst + 8192 + off,  gKL + tb + off);
            cpasync16(dst + 16384 + off, gVH + tb + off);
            cpasync16(dst + 24576 + off, gVL + tb + off);
        }
    }
    asm volatile("cp.async.commit_group;");

    float ofr[8][4];
    #pragma unroll
    for (int j = 0; j < 8; j++)
        #pragma unroll
        for (int e = 0; e < 4; e++) ofr[j][e] = 0.f;
    float mrow[2] = {-1e30f, -1e30f};
    float lrow[2] = {0.f, 0.f};

    const int rr0 = q0 + 16 * w + (lane >> 2);

    for (int it = 0; it < NTILES; it++) {
        const int k0 = it * TK;
        const uint32_t bufb = (uint32_t)(it & 1) * BUF;
        const uint32_t KHI = bufb, KLO = bufb + 8192, VHI = bufb + 16384, VLO = bufb + 24576;

        asm volatile("cp.async.wait_group 1;");
        __syncthreads();   // tile it resident and visible to all warps

        // ---- two 32-key halves ----
        #pragma unroll
        for (int hf = 0; hf < 2; hf++) {
            float2 bfr[4][2];
            int2   mfr[4][2];
            #pragma unroll
            for (int j = 0; j < 4; j++)
                #pragma unroll
                for (int p = 0; p < 2; p++) {
                    const int row = rr0 + 8 * p;
                    const int col = k0 + 32 * hf + 8 * j + (lane & 3) * 2;
                    bfr[j][p] = *reinterpret_cast<const float2*>(
                        gbias + ((size_t)bh * S + row) * S + col);
                    mfr[j][p] = *reinterpret_cast<const int2*>(
                        gmask + ((size_t)b * S + row) * S + col);
                }

            float sfr[4][4];
            #pragma unroll
            for (int j = 0; j < 4; j++)
                #pragma unroll
                for (int e = 0; e < 4; e++) sfr[j][e] = 0.f;

            #pragma unroll
            for (int ks = 0; ks < 4; ks++) {
                #pragma unroll
                for (int ii = 0; ii < 2; ii++) {
                    const int i = 2 * hf + ii;
                    const uint32_t off = swz((uint32_t)((16 * i + b_ro) * 128 + (2 * ks + b_ca) * 16));
                    uint32_t kh0, kh1, kh2, kh3, kl0, kl1, kl2, kl3;
                    ldsm4(kh0, kh1, kh2, kh3, smu + KHI + off);
                    ldsm4(kl0, kl1, kl2, kl3, smu + KLO + off);
                    mma16816(sfr[2 * ii],     qh[ks][0], qh[ks][1], qh[ks][2], qh[ks][3], kh0, kh1);
                    mma16816(sfr[2 * ii],     qh[ks][0], qh[ks][1], qh[ks][2], qh[ks][3], kl0, kl1);
                    mma16816(sfr[2 * ii],     ql[ks][0], ql[ks][1], ql[ks][2], ql[ks][3], kh0, kh1);
                    mma16816(sfr[2 * ii + 1], qh[ks][0], qh[ks][1], qh[ks][2], qh[ks][3], kh2, kh3);
                    mma16816(sfr[2 * ii + 1], qh[ks][0], qh[ks][1], qh[ks][2], qh[ks][3], kl2, kl3);
                    mma16816(sfr[2 * ii + 1], ql[ks][0], ql[ks][1], ql[ks][2], ql[ks][3], kh2, kh3);
                }
            }

            // bias, mask->0, online softmax (per row: 4 lanes)
            #pragma unroll
            for (int p = 0; p < 2; p++) {
                float mx = -1e30f;
                #pragma unroll
                for (int j = 0; j < 4; j++) {
                    const float2 bv = bfr[j][p];
                    const int2   mv = mfr[j][p];
                    float v0 = mv.x ? 0.0f : sfr[j][2 * p]     + bv.x;
                    float v1 = mv.y ? 0.0f : sfr[j][2 * p + 1] + bv.y;
                    sfr[j][2 * p] = v0; sfr[j][2 * p + 1] = v1;
                    mx = fmaxf(mx, fmaxf(v0, v1));
                }
                mx = fmaxf(mx, __shfl_xor_sync(0xffffffffu, mx, 1));
                mx = fmaxf(mx, __shfl_xor_sync(0xffffffffu, mx, 2));
                const float mnew = fmaxf(mrow[p], mx);
                const float corr = __expf(mrow[p] - mnew);
                mrow[p] = mnew;

                float rs = 0.f;
                #pragma unroll
                for (int j = 0; j < 4; j++) {
                    const float e0 = __expf(sfr[j][2 * p]     - mnew);
                    const float e1 = __expf(sfr[j][2 * p + 1] - mnew);
                    sfr[j][2 * p] = e0; sfr[j][2 * p + 1] = e1;
                    rs += e0 + e1;
                }
                rs += __shfl_xor_sync(0xffffffffu, rs, 1);
                rs += __shfl_xor_sync(0xffffffffu, rs, 2);
                lrow[p] = lrow[p] * corr + rs;
                #pragma unroll
                for (int j = 0; j < 8; j++) {
                    ofr[j][2 * p] *= corr; ofr[j][2 * p + 1] *= corr;
                }
            }

            // P fragments (registers only)
            uint32_t ph[2][4], pl[2][4];
            #pragma unroll
            for (int ksp = 0; ksp < 2; ksp++) {
                #pragma unroll
                for (int half = 0; half < 2; half++) {
                    const int j = 2 * ksp + half;
                    #pragma unroll
                    for (int p = 0; p < 2; p++) {
                        const float x = sfr[j][2 * p], y = sfr[j][2 * p + 1];
                        const __nv_bfloat16 hx = __float2bfloat16_rn(x), hy = __float2bfloat16_rn(y);
                        ph[ksp][half * 2 + p] =
                            (uint32_t)__bfloat16_as_ushort(hx) | ((uint32_t)__bfloat16_as_ushort(hy) << 16);
                        pl[ksp][half * 2 + p] =
                            pack_bf(x - __bfloat162float(hx), y - __bfloat162float(hy));
                    }
                }
            }

            // O += P V
            #pragma unroll
            for (int ksp = 0; ksp < 2; ksp++) {
                const int kb16 = 2 * hf + ksp;
                #pragma unroll
                for (int i = 0; i < 4; i++) {
                    const uint32_t off = swz((uint32_t)((16 * kb16 + v_ro) * 128 + (2 * i + v_ca) * 16));
                    uint32_t vh0, vh1, vh2, vh3, vl0, vl1, vl2, vl3;
                    ldsm4t(vh0, vh1, vh2, vh3, smu + VHI + off);
                    ldsm4t(vl0, vl1, vl2, vl3, smu + VLO + off);
                    mma16816(ofr[2 * i],     ph[ksp][0], ph[ksp][1], ph[ksp][2], ph[ksp][3], vh0, vh1);
                    mma16816(ofr[2 * i],     ph[ksp][0], ph[ksp][1], ph[ksp][2], ph[ksp][3], vl0, vl1);
                    mma16816(ofr[2 * i],     pl[ksp][0], pl[ksp][1], pl[ksp][2], pl[ksp][3], vh0, vh1);
                    mma16816(ofr[2 * i + 1], ph[ksp][0], ph[ksp][1], ph[ksp][2], ph[ksp][3], vh2, vh3);
                    mma16816(ofr[2 * i + 1], ph[ksp][0], ph[ksp][1], ph[ksp][2], ph[ksp][3], vl2, vl3);
                    mma16816(ofr[2 * i + 1], pl[ksp][0], pl[ksp][1], pl[ksp][2], pl[ksp][3], vh2, vh3);
                }
            }
        }

        __syncthreads();   // all warps done reading buf[it&1]
        if (it + 2 < NTILES) {
            const size_t tb = tile_base0 + (size_t)(it + 2) * TILE_BYTES;
            const uint32_t dst = smu + bufb;
            #pragma unroll
            for (int r = 0; r < 4; r++) {
                const int off = r * 2048 + tid * 16;
                cpasync16(dst + off,         gKH + tb + off);
                cpasync16(dst + 8192 + off,  gKL + tb + off);
                cpasync16(dst + 16384 + off, gVH + tb + off);
                cpasync16(dst + 24576 + off, gVL + tb + off);
            }
        }
        asm volatile("cp.async.commit_group;");
    }

    // ---- epilogue: normalize, store [B,S,H,D] ----
    const float inv0 = 1.0f / lrow[0];
    const float inv1 = 1.0f / lrow[1];
    #pragma unroll
    for (int j = 0; j < 8; j++) {
        const int d = 8 * j + (lane & 3) * 2;
        float2 w0 = make_float2(ofr[j][0] * inv0, ofr[j][1] * inv0);
        float2 w1 = make_float2(ofr[j][2] * inv1, ofr[j][3] * inv1);
        *reinterpret_cast<float2*>(gout + ((size_t)(b * S + rr0)     * H + h) * D + d) = w0;
        *reinterpret_cast<float2*>(gout + ((size_t)(b * S + rr0 + 8) * H + h) * D + d) = w1;
    }
}

extern "C" void kernel_launch(void* const* d_in, const int* in_sizes, int n_in,
                              void* d_out, int out_size) {
    const float* q    = (const float*)d_in[0];
    const float* k    = (const float*)d_in[1];
    const float* v    = (const float*)d_in[2];
    const float* bias = (const float*)d_in[3];
    const int*   mask = (const int*)d_in[4];
    float* out = (float*)d_out;

    split_kv_kernel<<<(B * H * S * 16) / 256, 256>>>(k, v);

    cudaFuncSetAttribute(attn_mma_kernel,
                         cudaFuncAttributeMaxDynamicSharedMemorySize, SMEM_BYTES);
    dim3 grid(B * H, S / TQ);
    attn_mma_kernel<<<grid, NT, SMEM_BYTES>>>(q, bias, mask, out);
}

// round 10
// speedup vs baseline: 3.9950x; 1.3049x over previous
#include <cuda_runtime.h>
#include <cuda_bf16.h>
#include <cstdint>

namespace {
constexpr int B  = 2;
constexpr int S  = 2048;
constexpr int H  = 16;
constexpr int D  = 64;
constexpr int TQ = 64;
constexpr int TK = 64;
constexpr int NT = 128;   // 4 warps
constexpr int HD = H * D;
constexpr int NTILES = S / TK;     // 32
constexpr int TILE_BYTES = 64 * 128;        // 8KB per split component
constexpr int BUF = 32768;
constexpr int SMEM_BYTES = 2 * BUF;         // 64KB
}

// Pre-split, pre-swizzled K/V tiles: [bh][tile] blocks of 8KB each.
__device__ __align__(16) unsigned char gKH[(size_t)B * H * NTILES * TILE_BYTES];
__device__ __align__(16) unsigned char gKL[(size_t)B * H * NTILES * TILE_BYTES];
__device__ __align__(16) unsigned char gVH[(size_t)B * H * NTILES * TILE_BYTES];
__device__ __align__(16) unsigned char gVL[(size_t)B * H * NTILES * TILE_BYTES];
// Packed mask: [B*S][NTILES] uint64, bit k of word t = mask[b][s][64t+k]  (1MB)
__device__ __align__(16) unsigned long long gPM[(size_t)B * S * NTILES];

__device__ __forceinline__ uint32_t swz(uint32_t off) { return off ^ ((off >> 3) & 0x70); }

__device__ __forceinline__ void cpasync16(uint32_t dst, const void* src) {
    asm volatile("cp.async.cg.shared.global [%0], [%1], 16;" :: "r"(dst), "l"(src));
}
__device__ __forceinline__ void ldsm4(uint32_t& r0, uint32_t& r1, uint32_t& r2, uint32_t& r3, uint32_t a) {
    asm volatile("ldmatrix.sync.aligned.m8n8.x4.shared.b16 {%0,%1,%2,%3},[%4];"
                 : "=r"(r0), "=r"(r1), "=r"(r2), "=r"(r3) : "r"(a));
}
__device__ __forceinline__ void ldsm4t(uint32_t& r0, uint32_t& r1, uint32_t& r2, uint32_t& r3, uint32_t a) {
    asm volatile("ldmatrix.sync.aligned.m8n8.x4.trans.shared.b16 {%0,%1,%2,%3},[%4];"
                 : "=r"(r0), "=r"(r1), "=r"(r2), "=r"(r3) : "r"(a));
}
__device__ __forceinline__ void mma16816(float c[4], uint32_t a0, uint32_t a1, uint32_t a2, uint32_t a3,
                                         uint32_t b0, uint32_t b1) {
    asm volatile("mma.sync.aligned.m16n8k16.row.col.f32.bf16.bf16.f32 "
                 "{%0,%1,%2,%3},{%4,%5,%6,%7},{%8,%9},{%0,%1,%2,%3};"
                 : "+f"(c[0]), "+f"(c[1]), "+f"(c[2]), "+f"(c[3])
                 : "r"(a0), "r"(a1), "r"(a2), "r"(a3), "r"(b0), "r"(b1));
}
__device__ __forceinline__ uint32_t pack_bf(float x, float y) {
    __nv_bfloat16 hx = __float2bfloat16_rn(x), hy = __float2bfloat16_rn(y);
    return (uint32_t)__bfloat16_as_ushort(hx) | ((uint32_t)__bfloat16_as_ushort(hy) << 16);
}
__device__ __forceinline__ void split4(float4 t, uint2& hv, uint2& lv) {
    __nv_bfloat16 h0 = __float2bfloat16_rn(t.x), h1 = __float2bfloat16_rn(t.y);
    __nv_bfloat16 h2 = __float2bfloat16_rn(t.z), h3 = __float2bfloat16_rn(t.w);
    hv.x = (uint32_t)__bfloat16_as_ushort(h0) | ((uint32_t)__bfloat16_as_ushort(h1) << 16);
    hv.y = (uint32_t)__bfloat16_as_ushort(h2) | ((uint32_t)__bfloat16_as_ushort(h3) << 16);
    lv.x = pack_bf(t.x - __bfloat162float(h0), t.y - __bfloat162float(h1));
    lv.y = pack_bf(t.z - __bfloat162float(h2), t.w - __bfloat162float(h3));
}

// ---- prepass A: K/V fp32 -> split bf16, swizzled 8KB tile blocks ----
__global__ void __launch_bounds__(256)
split_kv_kernel(const float* __restrict__ gk, const float* __restrict__ gv)
{
    const int idx = blockIdx.x * 256 + threadIdx.x;
    const int c16 = idx & 15;
    const int s   = (idx >> 4) & (S - 1);
    const int bh  = idx >> 15;
    const int b = bh >> 4, h = bh & 15;

    const size_t gsrc = ((size_t)(b * S + s) * H + h) * D + c16 * 4;
    const float4 kt = *reinterpret_cast<const float4*>(gk + gsrc);
    const float4 vt = *reinterpret_cast<const float4*>(gv + gsrc);

    const size_t base = ((size_t)(bh * NTILES + (s >> 6)) << 13)
                      + swz((uint32_t)((s & 63) * 128 + c16 * 8));
    uint2 hv, lv;
    split4(kt, hv, lv);
    *reinterpret_cast<uint2*>(gKH + base) = hv;
    *reinterpret_cast<uint2*>(gKL + base) = lv;
    split4(vt, hv, lv);
    *reinterpret_cast<uint2*>(gVH + base) = hv;
    *reinterpret_cast<uint2*>(gVL + base) = lv;
}

// ---- prepass B: pack mask into uint64 bitmaps ----
__global__ void __launch_bounds__(256)
pack_mask_kernel(const int* __restrict__ gmask)
{
    const int gw   = (blockIdx.x * 256 + threadIdx.x) >> 5;  // [0, B*S*NTILES)
    const int lane = threadIdx.x & 31;
    const int row   = gw >> 5;           // 0..B*S-1
    const int chunk = gw & 31;
    const int* mr = gmask + (size_t)row * S + chunk * 64;
    const unsigned lo = __ballot_sync(0xffffffffu, mr[lane]        != 0);
    const unsigned hi = __ballot_sync(0xffffffffu, mr[lane + 32]   != 0);
    if (lane == 0)
        gPM[(size_t)row * NTILES + chunk] = ((unsigned long long)hi << 32) | lo;
}

__global__ void __launch_bounds__(NT, 3)
attn_mma_kernel(const float* __restrict__ gq, const float* __restrict__ gbias,
                float* __restrict__ gout)
{
    extern __shared__ char smem[];
    const uint32_t smu = (uint32_t)__cvta_generic_to_shared(smem);

    const int tid  = threadIdx.x;
    const int lane = tid & 31;
    const int w    = tid >> 5;
    const int bh   = blockIdx.x;
    const int b    = bh >> 4;
    const int h    = bh & 15;
    const int q0   = blockIdx.y * TQ;

    const int sub = lane >> 3, lr = lane & 7;
    const int a_row = 16 * w + lr + ((sub & 1) << 3);
    const int a_ca  = sub >> 1;
    const int b_ro  = lr + ((sub >> 1) << 3);
    const int b_ca  = sub & 1;
    const int v_ro  = lr + ((sub & 1) << 3);
    const int v_ca  = sub >> 1;

    const size_t tile_base0 = (size_t)(bh * NTILES) << 13;

    // issue tile0 copy into buf0 (overlaps Q staging)
    {
        const uint32_t dst = smu;
        #pragma unroll
        for (int r = 0; r < 4; r++) {
            const int off = r * 2048 + tid * 16;
            cpasync16(dst + off,         gKH + tile_base0 + off);
            cpasync16(dst + 8192 + off,  gKL + tile_base0 + off);
            cpasync16(dst + 16384 + off, gVH + tile_base0 + off);
            cpasync16(dst + 24576 + off, gVL + tile_base0 + off);
        }
    }
    asm volatile("cp.async.commit_group;");

    // ---- stage Q (x8, split) into buf1, take register fragments ----
    {
        const float* qb = gq + ((size_t)(b * S + q0) * H + h) * D;
        #pragma unroll
        for (int r = 0; r < 8; r++) {
            const int idx = r * NT + tid;
            const int row = idx >> 4, c16 = idx & 15;
            float4 t = *reinterpret_cast<const float4*>(qb + (size_t)row * HD + c16 * 4);
            t.x *= 8.0f; t.y *= 8.0f; t.z *= 8.0f; t.w *= 8.0f;
            uint2 hv, lv;
            split4(t, hv, lv);
            const uint32_t so = swz((uint32_t)(row * 128 + c16 * 8));
            *reinterpret_cast<uint2*>(smem + BUF + so)        = hv;
            *reinterpret_cast<uint2*>(smem + BUF + 8192 + so) = lv;
        }
    }
    __syncthreads();

    uint32_t qh[4][4], ql[4][4];
    #pragma unroll
    for (int ks = 0; ks < 4; ks++) {
        const uint32_t off = swz((uint32_t)(a_row * 128 + (2 * ks + a_ca) * 16));
        ldsm4(qh[ks][0], qh[ks][1], qh[ks][2], qh[ks][3], smu + BUF + off);
        ldsm4(ql[ks][0], ql[ks][1], ql[ks][2], ql[ks][3], smu + BUF + 8192 + off);
    }
    __syncthreads();

    // issue tile1 copy into buf1
    {
        const size_t tb = tile_base0 + TILE_BYTES;
        const uint32_t dst = smu + BUF;
        #pragma unroll
        for (int r = 0; r < 4; r++) {
            const int off = r * 2048 + tid * 16;
            cpasync16(dst + off,         gKH + tb + off);
            cpasync16(dst + 8192 + off,  gKL + tb + off);
            cpasync16(dst + 16384 + off, gVH + tb + off);
            cpasync16(dst + 24576 + off, gVL + tb + off);
        }
    }
    asm volatile("cp.async.commit_group;");

    float ofr[8][4];
    #pragma unroll
    for (int j = 0; j < 8; j++)
        #pragma unroll
        for (int e = 0; e < 4; e++) ofr[j][e] = 0.f;
    float mrow[2] = {-1e30f, -1e30f};
    float lrow[2] = {0.f, 0.f};

    const int rr0 = q0 + 16 * w + (lane >> 2);
    const int cq  = (lane & 3) * 2;                        // col pair base within 8-block
    const unsigned long long* pm0 = gPM + (size_t)(b * S + rr0) * NTILES;
    const unsigned long long* pm1 = gPM + (size_t)(b * S + rr0 + 8) * NTILES;

    for (int it = 0; it < NTILES; it++) {
        const int k0 = it * TK;
        const uint32_t bufb = (uint32_t)(it & 1) * BUF;
        const uint32_t KHI = bufb, KLO = bufb + 8192, VHI = bufb + 16384, VLO = bufb + 24576;

        asm volatile("cp.async.wait_group 1;");
        __syncthreads();

        // packed mask row-words (broadcast within quad) + bias loads for keys 0..31
        const unsigned long long mw[2] = {pm0[it], pm1[it]};
        float2 bfr0[4][2];
        #pragma unroll
        for (int j = 0; j < 4; j++)
            #pragma unroll
            for (int p = 0; p < 2; p++)
                bfr0[j][p] = *reinterpret_cast<const float2*>(
                    gbias + ((size_t)bh * S + rr0 + 8 * p) * S + k0 + 8 * j + cq);

        float sfr[8][4];
        #pragma unroll
        for (int j = 0; j < 8; j++)
            #pragma unroll
            for (int e = 0; e < 4; e++) sfr[j][e] = 0.f;

        // ---- QK keys 0..31 (covers bfr0 latency) ----
        #pragma unroll
        for (int ks = 0; ks < 4; ks++)
            #pragma unroll
            for (int i = 0; i < 2; i++) {
                const uint32_t off = swz((uint32_t)((16 * i + b_ro) * 128 + (2 * ks + b_ca) * 16));
                uint32_t kh0, kh1, kh2, kh3, kl0, kl1, kl2, kl3;
                ldsm4(kh0, kh1, kh2, kh3, smu + KHI + off);
                ldsm4(kl0, kl1, kl2, kl3, smu + KLO + off);
                mma16816(sfr[2 * i],     qh[ks][0], qh[ks][1], qh[ks][2], qh[ks][3], kh0, kh1);
                mma16816(sfr[2 * i],     qh[ks][0], qh[ks][1], qh[ks][2], qh[ks][3], kl0, kl1);
                mma16816(sfr[2 * i],     ql[ks][0], ql[ks][1], ql[ks][2], ql[ks][3], kh0, kh1);
                mma16816(sfr[2 * i + 1], qh[ks][0], qh[ks][1], qh[ks][2], qh[ks][3], kh2, kh3);
                mma16816(sfr[2 * i + 1], qh[ks][0], qh[ks][1], qh[ks][2], qh[ks][3], kl2, kl3);
                mma16816(sfr[2 * i + 1], ql[ks][0], ql[ks][1], ql[ks][2], ql[ks][3], kh2, kh3);
            }

        // bias loads for keys 32..63 (covered by second QK batch)
        float2 bfr1[4][2];
        #pragma unroll
        for (int j = 0; j < 4; j++)
            #pragma unroll
            for (int p = 0; p < 2; p++)
                bfr1[j][p] = *reinterpret_cast<const float2*>(
                    gbias + ((size_t)bh * S + rr0 + 8 * p) * S + k0 + 32 + 8 * j + cq);

        // ---- QK keys 32..63 ----
        #pragma unroll
        for (int ks = 0; ks < 4; ks++)
            #pragma unroll
            for (int i = 2; i < 4; i++) {
                const uint32_t off = swz((uint32_t)((16 * i + b_ro) * 128 + (2 * ks + b_ca) * 16));
                uint32_t kh0, kh1, kh2, kh3, kl0, kl1, kl2, kl3;
                ldsm4(kh0, kh1, kh2, kh3, smu + KHI + off);
                ldsm4(kl0, kl1, kl2, kl3, smu + KLO + off);
                mma16816(sfr[2 * i],     qh[ks][0], qh[ks][1], qh[ks][2], qh[ks][3], kh0, kh1);
                mma16816(sfr[2 * i],     qh[ks][0], qh[ks][1], qh[ks][2], qh[ks][3], kl0, kl1);
                mma16816(sfr[2 * i],     ql[ks][0], ql[ks][1], ql[ks][2], ql[ks][3], kh0, kh1);
                mma16816(sfr[2 * i + 1], qh[ks][0], qh[ks][1], qh[ks][2], qh[ks][3], kh2, kh3);
                mma16816(sfr[2 * i + 1], qh[ks][0], qh[ks][1], qh[ks][2], qh[ks][3], kl2, kl3);
                mma16816(sfr[2 * i + 1], ql[ks][0], ql[ks][1], ql[ks][2], ql[ks][3], kh2, kh3);
            }

        // ---- apply bias + packed mask (all 64 keys) ----
        #pragma unroll
        for (int j = 0; j < 8; j++) {
            const float2* bp = (j < 4) ? bfr0[j] : bfr1[j - 4];
            const int base = 8 * j + cq;
            #pragma unroll
            for (int p = 0; p < 2; p++) {
                const unsigned mb = (unsigned)(mw[p] >> base);
                sfr[j][2 * p]     = (mb & 1u) ? 0.0f : sfr[j][2 * p]     + bp[p].x;
                sfr[j][2 * p + 1] = (mb & 2u) ? 0.0f : sfr[j][2 * p + 1] + bp[p].y;
            }
        }

        // ---- single online softmax over all 64 keys ----
        #pragma unroll
        for (int p = 0; p < 2; p++) {
            float mx = -1e30f;
            #pragma unroll
            for (int j = 0; j < 8; j++)
                mx = fmaxf(mx, fmaxf(sfr[j][2 * p], sfr[j][2 * p + 1]));
            mx = fmaxf(mx, __shfl_xor_sync(0xffffffffu, mx, 1));
            mx = fmaxf(mx, __shfl_xor_sync(0xffffffffu, mx, 2));
            const float mnew = fmaxf(mrow[p], mx);
            const float corr = __expf(mrow[p] - mnew);
            mrow[p] = mnew;

            float rs = 0.f;
            #pragma unroll
            for (int j = 0; j < 8; j++) {
                const float e0 = __expf(sfr[j][2 * p]     - mnew);
                const float e1 = __expf(sfr[j][2 * p + 1] - mnew);
                sfr[j][2 * p] = e0; sfr[j][2 * p + 1] = e1;
                rs += e0 + e1;
            }
            rs += __shfl_xor_sync(0xffffffffu, rs, 1);
            rs += __shfl_xor_sync(0xffffffffu, rs, 2);
            lrow[p] = lrow[p] * corr + rs;
            #pragma unroll
            for (int j = 0; j < 8; j++) {
                ofr[j][2 * p] *= corr; ofr[j][2 * p + 1] *= corr;
            }
        }

        // ---- PV: per k16 block, convert P then MMA (keeps P regs low) ----
        #pragma unroll
        for (int ksp = 0; ksp < 4; ksp++) {
            uint32_t ph[4], pl[4];
            #pragma unroll
            for (int half = 0; half < 2; half++) {
                const int j = 2 * ksp + half;
                #pragma unroll
                for (int p = 0; p < 2; p++) {
                    const float x = sfr[j][2 * p], y = sfr[j][2 * p + 1];
                    const __nv_bfloat16 hx = __float2bfloat16_rn(x), hy = __float2bfloat16_rn(y);
                    ph[half * 2 + p] =
                        (uint32_t)__bfloat16_as_ushort(hx) | ((uint32_t)__bfloat16_as_ushort(hy) << 16);
                    pl[half * 2 + p] =
                        pack_bf(x - __bfloat162float(hx), y - __bfloat162float(hy));
                }
            }
            #pragma unroll
            for (int i = 0; i < 4; i++) {
                const uint32_t off = swz((uint32_t)((16 * ksp + v_ro) * 128 + (2 * i + v_ca) * 16));
                uint32_t vh0, vh1, vh2, vh3, vl0, vl1, vl2, vl3;
                ldsm4t(vh0, vh1, vh2, vh3, smu + VHI + off);
                ldsm4t(vl0, vl1, vl2, vl3, smu + VLO + off);
                mma16816(ofr[2 * i],     ph[0], ph[1], ph[2], ph[3], vh0, vh1);
                mma16816(ofr[2 * i],     ph[0], ph[1], ph[2], ph[3], vl0, vl1);
                mma16816(ofr[2 * i],     pl[0], pl[1], pl[2], pl[3], vh0, vh1);
                mma16816(ofr[2 * i + 1], ph[0], ph[1], ph[2], ph[3], vh2, vh3);
                mma16816(ofr[2 * i + 1], ph[0], ph[1], ph[2], ph[3], vl2, vl3);
                mma16816(ofr[2 * i + 1], pl[0], pl[1], pl[2], pl[3], vh2, vh3);
            }
        }

        __syncthreads();   // all warps done reading buf[it&1]
        if (it + 2 < NTILES) {
            const size_t tb = tile_base0 + (size_t)(it + 2) * TILE_BYTES;
            const uint32_t dst = smu + bufb;
            #pragma unroll
            for (int r = 0; r < 4; r++) {
                const int off = r * 2048 + tid * 16;
                cpasync16(dst + off,         gKH + tb + off);
                cpasync16(dst + 8192 + off,  gKL + tb + off);
                cpasync16(dst + 16384 + off, gVH + tb + off);
                cpasync16(dst + 24576 + off, gVL + tb + off);
            }
        }
        asm volatile("cp.async.commit_group;");
    }

    // ---- epilogue: normalize, store [B,S,H,D] ----
    const float inv0 = 1.0f / lrow[0];
    const float inv1 = 1.0f / lrow[1];
    #pragma unroll
    for (int j = 0; j < 8; j++) {
        const int d = 8 * j + cq;
        float2 w0 = make_float2(ofr[j][0] * inv0, ofr[j][1] * inv0);
        float2 w1 = make_float2(ofr[j][2] * inv1, ofr[j][3] * inv1);
        *reinterpret_cast<float2*>(gout + ((size_t)(b * S + rr0)     * H + h) * D + d) = w0;
        *reinterpret_cast<float2*>(gout + ((size_t)(b * S + rr0 + 8) * H + h) * D + d) = w1;
    }
}

extern "C" void kernel_launch(void* const* d_in, const int* in_sizes, int n_in,
                              void* d_out, int out_size) {
    const float* q    = (const float*)d_in[0];
    const float* k    = (const float*)d_in[1];
    const float* v    = (const float*)d_in[2];
    const float* bias = (const float*)d_in[3];
    const int*   mask = (const int*)d_in[4];
    float* out = (float*)d_out;

    split_kv_kernel<<<(B * H * S * 16) / 256, 256>>>(k, v);
    pack_mask_kernel<<<(B * S * NTILES * 32) / 256, 256>>>(mask);

    cudaFuncSetAttribute(attn_mma_kernel,
                         cudaFuncAttributeMaxDynamicSharedMemorySize, SMEM_BYTES);
    dim3 grid(B * H, S / TQ);
    attn_mma_kernel<<<grid, NT, SMEM_BYTES>>>(q, bias, out);
}

// round 11
// speedup vs baseline: 4.3825x; 1.0970x over previous
#include <cuda_runtime.h>
#include <cuda_bf16.h>
#include <cstdint>

namespace {
constexpr int B  = 2;
constexpr int S  = 2048;
constexpr int H  = 16;
constexpr int D  = 64;
constexpr int TQ = 64;
constexpr int TK = 64;
constexpr int NT = 128;   // 4 warps
constexpr int HD = H * D;
constexpr int NTILES = S / TK;     // 32
constexpr int TILE_BYTES = 64 * 128;
constexpr int BUF = 32768;
constexpr int SMEM_BYTES = 2 * BUF;
constexpr float LOG2E = 1.4426950408889634f;
}

// Pre-split, pre-swizzled K/V tiles: [bh][tile] blocks of 8KB each.
__device__ __align__(16) unsigned char gKH[(size_t)B * H * NTILES * TILE_BYTES];
__device__ __align__(16) unsigned char gKL[(size_t)B * H * NTILES * TILE_BYTES];
__device__ __align__(16) unsigned char gVH[(size_t)B * H * NTILES * TILE_BYTES];
__device__ __align__(16) unsigned char gVL[(size_t)B * H * NTILES * TILE_BYTES];
// Packed mask: [B*S][NTILES] uint64
__device__ __align__(16) unsigned long long gPM[(size_t)B * S * NTILES];

__device__ __forceinline__ uint32_t swz(uint32_t off) { return off ^ ((off >> 3) & 0x70); }

__device__ __forceinline__ void cpasync16(uint32_t dst, const void* src) {
    asm volatile("cp.async.cg.shared.global [%0], [%1], 16;" :: "r"(dst), "l"(src));
}
__device__ __forceinline__ void ldsm4(uint32_t& r0, uint32_t& r1, uint32_t& r2, uint32_t& r3, uint32_t a) {
    asm volatile("ldmatrix.sync.aligned.m8n8.x4.shared.b16 {%0,%1,%2,%3},[%4];"
                 : "=r"(r0), "=r"(r1), "=r"(r2), "=r"(r3) : "r"(a));
}
__device__ __forceinline__ void ldsm4t(uint32_t& r0, uint32_t& r1, uint32_t& r2, uint32_t& r3, uint32_t a) {
    asm volatile("ldmatrix.sync.aligned.m8n8.x4.trans.shared.b16 {%0,%1,%2,%3},[%4];"
                 : "=r"(r0), "=r"(r1), "=r"(r2), "=r"(r3) : "r"(a));
}
__device__ __forceinline__ void mma16816(float c[4], uint32_t a0, uint32_t a1, uint32_t a2, uint32_t a3,
                                         uint32_t b0, uint32_t b1) {
    asm volatile("mma.sync.aligned.m16n8k16.row.col.f32.bf16.bf16.f32 "
                 "{%0,%1,%2,%3},{%4,%5,%6,%7},{%8,%9},{%0,%1,%2,%3};"
                 : "+f"(c[0]), "+f"(c[1]), "+f"(c[2]), "+f"(c[3])
                 : "r"(a0), "r"(a1), "r"(a2), "r"(a3), "r"(b0), "r"(b1));
}
__device__ __forceinline__ float ex2(float x) {
    float y; asm("ex2.approx.f32 %0, %1;" : "=f"(y) : "f"(x)); return y;
}
// packed bf16x2: low half = lo, high half = hi (cvt: first src -> high half)
__device__ __forceinline__ uint32_t cvt_bf2(float hi, float lo) {
    uint32_t r; asm("cvt.rn.bf16x2.f32 %0, %1, %2;" : "=r"(r) : "f"(hi), "f"(lo)); return r;
}
__device__ __forceinline__ uint32_t pack_bf(float x, float y) {
    __nv_bfloat16 hx = __float2bfloat16_rn(x), hy = __float2bfloat16_rn(y);
    return (uint32_t)__bfloat16_as_ushort(hx) | ((uint32_t)__bfloat16_as_ushort(hy) << 16);
}
__device__ __forceinline__ void split4(float4 t, uint2& hv, uint2& lv) {
    __nv_bfloat16 h0 = __float2bfloat16_rn(t.x), h1 = __float2bfloat16_rn(t.y);
    __nv_bfloat16 h2 = __float2bfloat16_rn(t.z), h3 = __float2bfloat16_rn(t.w);
    hv.x = (uint32_t)__bfloat16_as_ushort(h0) | ((uint32_t)__bfloat16_as_ushort(h1) << 16);
    hv.y = (uint32_t)__bfloat16_as_ushort(h2) | ((uint32_t)__bfloat16_as_ushort(h3) << 16);
    lv.x = pack_bf(t.x - __bfloat162float(h0), t.y - __bfloat162float(h1));
    lv.y = pack_bf(t.z - __bfloat162float(h2), t.w - __bfloat162float(h3));
}

// ---- prepass A: K/V fp32 -> split bf16, swizzled 8KB tile blocks ----
__global__ void __launch_bounds__(256)
split_kv_kernel(const float* __restrict__ gk, const float* __restrict__ gv)
{
    const int idx = blockIdx.x * 256 + threadIdx.x;
    const int c16 = idx & 15;
    const int s   = (idx >> 4) & (S - 1);
    const int bh  = idx >> 15;
    const int b = bh >> 4, h = bh & 15;

    const size_t gsrc = ((size_t)(b * S + s) * H + h) * D + c16 * 4;
    const float4 kt = *reinterpret_cast<const float4*>(gk + gsrc);
    const float4 vt = *reinterpret_cast<const float4*>(gv + gsrc);

    const size_t base = ((size_t)(bh * NTILES + (s >> 6)) << 13)
                      + swz((uint32_t)((s & 63) * 128 + c16 * 8));
    uint2 hv, lv;
    split4(kt, hv, lv);
    *reinterpret_cast<uint2*>(gKH + base) = hv;
    *reinterpret_cast<uint2*>(gKL + base) = lv;
    split4(vt, hv, lv);
    *reinterpret_cast<uint2*>(gVH + base) = hv;
    *reinterpret_cast<uint2*>(gVL + base) = lv;
}

// ---- prepass B: pack mask into uint64 bitmaps ----
__global__ void __launch_bounds__(256)
pack_mask_kernel(const int* __restrict__ gmask)
{
    const int gw   = (blockIdx.x * 256 + threadIdx.x) >> 5;
    const int lane = threadIdx.x & 31;
    const int row   = gw >> 5;
    const int chunk = gw & 31;
    const int* mr = gmask + (size_t)row * S + chunk * 64;
    const unsigned lo = __ballot_sync(0xffffffffu, mr[lane]      != 0);
    const unsigned hi = __ballot_sync(0xffffffffu, mr[lane + 32] != 0);
    if (lane == 0)
        gPM[(size_t)row * NTILES + chunk] = ((unsigned long long)hi << 32) | lo;
}

__global__ void __launch_bounds__(NT, 3)
attn_mma_kernel(const float* __restrict__ gq, const float* __restrict__ gbias,
                float* __restrict__ gout)
{
    extern __shared__ char smem[];
    const uint32_t smu = (uint32_t)__cvta_generic_to_shared(smem);

    const int tid  = threadIdx.x;
    const int lane = tid & 31;
    const int w    = tid >> 5;
    const int bh   = blockIdx.x;
    const int b    = bh >> 4;
    const int h    = bh & 15;
    const int q0   = blockIdx.y * TQ;

    const int sub = lane >> 3, lr = lane & 7;
    const int a_row = 16 * w + lr + ((sub & 1) << 3);
    const int a_ca  = sub >> 1;
    const int b_ro  = lr + ((sub >> 1) << 3);
    const int b_ca  = sub & 1;
    const int v_ro  = lr + ((sub & 1) << 3);
    const int v_ca  = sub >> 1;

    const size_t tile_base0 = (size_t)(bh * NTILES) << 13;

    // issue tile0 copy into buf0 (overlaps Q staging)
    {
        const uint32_t dst = smu;
        #pragma unroll
        for (int r = 0; r < 4; r++) {
            const int off = r * 2048 + tid * 16;
            cpasync16(dst + off,         gKH + tile_base0 + off);
            cpasync16(dst + 8192 + off,  gKL + tile_base0 + off);
            cpasync16(dst + 16384 + off, gVH + tile_base0 + off);
            cpasync16(dst + 24576 + off, gVL + tile_base0 + off);
        }
    }
    asm volatile("cp.async.commit_group;");

    // ---- stage Q (x 8*log2e, split) into buf1, take register fragments ----
    {
        const float* qb = gq + ((size_t)(b * S + q0) * H + h) * D;
        const float qs = 8.0f * LOG2E;
        #pragma unroll
        for (int r = 0; r < 8; r++) {
            const int idx = r * NT + tid;
            const int row = idx >> 4, c16 = idx & 15;
            float4 t = *reinterpret_cast<const float4*>(qb + (size_t)row * HD + c16 * 4);
            t.x *= qs; t.y *= qs; t.z *= qs; t.w *= qs;
            uint2 hv, lv;
            split4(t, hv, lv);
            const uint32_t so = swz((uint32_t)(row * 128 + c16 * 8));
            *reinterpret_cast<uint2*>(smem + BUF + so)        = hv;
            *reinterpret_cast<uint2*>(smem + BUF + 8192 + so) = lv;
        }
    }
    __syncthreads();

    uint32_t qh[4][4], ql[4][4];
    #pragma unroll
    for (int ks = 0; ks < 4; ks++) {
        const uint32_t off = swz((uint32_t)(a_row * 128 + (2 * ks + a_ca) * 16));
        ldsm4(qh[ks][0], qh[ks][1], qh[ks][2], qh[ks][3], smu + BUF + off);
        ldsm4(ql[ks][0], ql[ks][1], ql[ks][2], ql[ks][3], smu + BUF + 8192 + off);
    }
    __syncthreads();

    // issue tile1 copy into buf1
    {
        const size_t tb = tile_base0 + TILE_BYTES;
        const uint32_t dst = smu + BUF;
        #pragma unroll
        for (int r = 0; r < 4; r++) {
            const int off = r * 2048 + tid * 16;
            cpasync16(dst + off,         gKH + tb + off);
            cpasync16(dst + 8192 + off,  gKL + tb + off);
            cpasync16(dst + 16384 + off, gVH + tb + off);
            cpasync16(dst + 24576 + off, gVL + tb + off);
        }
    }
    asm volatile("cp.async.commit_group;");

    float ofr[8][4];
    #pragma unroll
    for (int j = 0; j < 8; j++)
        #pragma unroll
        for (int e = 0; e < 4; e++) ofr[j][e] = 0.f;
    float mrow[2] = {-1e30f, -1e30f};   // log2-domain running max
    float lrow[2] = {0.f, 0.f};

    const int rr0 = q0 + 16 * w + (lane >> 2);
    const int cq  = (lane & 3) * 2;
    const unsigned long long* pm0 = gPM + (size_t)(b * S + rr0) * NTILES;
    const unsigned long long* pm1 = gPM + (size_t)(b * S + rr0 + 8) * NTILES;

    for (int it = 0; it < NTILES; it++) {
        const int k0 = it * TK;
        const uint32_t bufb = (uint32_t)(it & 1) * BUF;
        const uint32_t KHI = bufb, KLO = bufb + 8192, VHI = bufb + 16384, VLO = bufb + 24576;

        asm volatile("cp.async.wait_group 1;");
        __syncthreads();

        const unsigned long long mw[2] = {pm0[it], pm1[it]};
        float2 bfr0[4][2];
        #pragma unroll
        for (int j = 0; j < 4; j++)
            #pragma unroll
            for (int p = 0; p < 2; p++)
                bfr0[j][p] = *reinterpret_cast<const float2*>(
                    gbias + ((size_t)bh * S + rr0 + 8 * p) * S + k0 + 8 * j + cq);

        float sfr[8][4];
        #pragma unroll
        for (int j = 0; j < 8; j++)
            #pragma unroll
            for (int e = 0; e < 4; e++) sfr[j][e] = 0.f;

        // ---- QK keys 0..31 ----
        #pragma unroll
        for (int ks = 0; ks < 4; ks++)
            #pragma unroll
            for (int i = 0; i < 2; i++) {
                const uint32_t off = swz((uint32_t)((16 * i + b_ro) * 128 + (2 * ks + b_ca) * 16));
                uint32_t kh0, kh1, kh2, kh3, kl0, kl1, kl2, kl3;
                ldsm4(kh0, kh1, kh2, kh3, smu + KHI + off);
                ldsm4(kl0, kl1, kl2, kl3, smu + KLO + off);
                mma16816(sfr[2 * i],     qh[ks][0], qh[ks][1], qh[ks][2], qh[ks][3], kh0, kh1);
                mma16816(sfr[2 * i],     qh[ks][0], qh[ks][1], qh[ks][2], qh[ks][3], kl0, kl1);
                mma16816(sfr[2 * i],     ql[ks][0], ql[ks][1], ql[ks][2], ql[ks][3], kh0, kh1);
                mma16816(sfr[2 * i + 1], qh[ks][0], qh[ks][1], qh[ks][2], qh[ks][3], kh2, kh3);
                mma16816(sfr[2 * i + 1], qh[ks][0], qh[ks][1], qh[ks][2], qh[ks][3], kl2, kl3);
                mma16816(sfr[2 * i + 1], ql[ks][0], ql[ks][1], ql[ks][2], ql[ks][3], kh2, kh3);
            }

        float2 bfr1[4][2];
        #pragma unroll
        for (int j = 0; j < 4; j++)
            #pragma unroll
            for (int p = 0; p < 2; p++)
                bfr1[j][p] = *reinterpret_cast<const float2*>(
                    gbias + ((size_t)bh * S + rr0 + 8 * p) * S + k0 + 32 + 8 * j + cq);

        // ---- QK keys 32..63 ----
        #pragma unroll
        for (int ks = 0; ks < 4; ks++)
            #pragma unroll
            for (int i = 2; i < 4; i++) {
                const uint32_t off = swz((uint32_t)((16 * i + b_ro) * 128 + (2 * ks + b_ca) * 16));
                uint32_t kh0, kh1, kh2, kh3, kl0, kl1, kl2, kl3;
                ldsm4(kh0, kh1, kh2, kh3, smu + KHI + off);
                ldsm4(kl0, kl1, kl2, kl3, smu + KLO + off);
                mma16816(sfr[2 * i],     qh[ks][0], qh[ks][1], qh[ks][2], qh[ks][3], kh0, kh1);
                mma16816(sfr[2 * i],     qh[ks][0], qh[ks][1], qh[ks][2], qh[ks][3], kl0, kl1);
                mma16816(sfr[2 * i],     ql[ks][0], ql[ks][1], ql[ks][2], ql[ks][3], kh0, kh1);
                mma16816(sfr[2 * i + 1], qh[ks][0], qh[ks][1], qh[ks][2], qh[ks][3], kh2, kh3);
                mma16816(sfr[2 * i + 1], qh[ks][0], qh[ks][1], qh[ks][2], qh[ks][3], kl2, kl3);
                mma16816(sfr[2 * i + 1], ql[ks][0], ql[ks][1], ql[ks][2], ql[ks][3], kh2, kh3);
            }

        // ---- bias (x log2e via FMA) + packed mask ----
        #pragma unroll
        for (int j = 0; j < 8; j++) {
            const float2* bp = (j < 4) ? bfr0[j] : bfr1[j - 4];
            const int base = 8 * j + cq;
            #pragma unroll
            for (int p = 0; p < 2; p++) {
                const unsigned mb = (unsigned)(mw[p] >> base);
                sfr[j][2 * p]     = (mb & 1u) ? 0.0f : fmaf(bp[p].x, LOG2E, sfr[j][2 * p]);
                sfr[j][2 * p + 1] = (mb & 2u) ? 0.0f : fmaf(bp[p].y, LOG2E, sfr[j][2 * p + 1]);
            }
        }

        // ---- single online softmax (log2 domain, EX2 only) ----
        float mold[2], mnew2[2], rs2[2];
        #pragma unroll
        for (int p = 0; p < 2; p++) {
            float mx = -1e30f;
            #pragma unroll
            for (int j = 0; j < 8; j++)
                mx = fmaxf(mx, fmaxf(sfr[j][2 * p], sfr[j][2 * p + 1]));
            mx = fmaxf(mx, __shfl_xor_sync(0xffffffffu, mx, 1));
            mx = fmaxf(mx, __shfl_xor_sync(0xffffffffu, mx, 2));
            mold[p] = mrow[p];
            const float mnew = fmaxf(mrow[p], mx);
            mrow[p] = mnew;
            mnew2[p] = mnew;

            float rs = 0.f;
            #pragma unroll
            for (int j = 0; j < 8; j++) {
                const float e0 = ex2(sfr[j][2 * p]     - mnew);
                const float e1 = ex2(sfr[j][2 * p + 1] - mnew);
                sfr[j][2 * p] = e0; sfr[j][2 * p + 1] = e1;
                rs += e0 + e1;
            }
            rs += __shfl_xor_sync(0xffffffffu, rs, 1);
            rs += __shfl_xor_sync(0xffffffffu, rs, 2);
            rs2[p] = rs;
        }

        // lazy rescale: skip the 64-FMA ofr rescale when no row max moved (warp-uniform)
        const bool moved = (mnew2[0] != mold[0]) || (mnew2[1] != mold[1]);
        if (__any_sync(0xffffffffu, moved)) {
            const float c0 = ex2(mold[0] - mnew2[0]);
            const float c1 = ex2(mold[1] - mnew2[1]);
            lrow[0] = lrow[0] * c0 + rs2[0];
            lrow[1] = lrow[1] * c1 + rs2[1];
            #pragma unroll
            for (int j = 0; j < 8; j++) {
                ofr[j][0] *= c0; ofr[j][1] *= c0;
                ofr[j][2] *= c1; ofr[j][3] *= c1;
            }
        } else {
            lrow[0] += rs2[0];
            lrow[1] += rs2[1];
        }

        // ---- PV: per k16 block, lean P split (cvt.bf16x2 + bit ops) ----
        #pragma unroll
        for (int ksp = 0; ksp < 4; ksp++) {
            uint32_t ph[4], pl[4];
            #pragma unroll
            for (int half = 0; half < 2; half++) {
                const int j = 2 * ksp + half;
                #pragma unroll
                for (int p = 0; p < 2; p++) {
                    const float x = sfr[j][2 * p], y = sfr[j][2 * p + 1];
                    const uint32_t hp = cvt_bf2(y, x);
                    const float fx = __uint_as_float(hp << 16);
                    const float fy = __uint_as_float(hp & 0xFFFF0000u);
                    ph[half * 2 + p] = hp;
                    pl[half * 2 + p] = cvt_bf2(y - fy, x - fx);
                }
            }
            #pragma unroll
            for (int i = 0; i < 4; i++) {
                const uint32_t off = swz((uint32_t)((16 * ksp + v_ro) * 128 + (2 * i + v_ca) * 16));
                uint32_t vh0, vh1, vh2, vh3, vl0, vl1, vl2, vl3;
                ldsm4t(vh0, vh1, vh2, vh3, smu + VHI + off);
                ldsm4t(vl0, vl1, vl2, vl3, smu + VLO + off);
                mma16816(ofr[2 * i],     ph[0], ph[1], ph[2], ph[3], vh0, vh1);
                mma16816(ofr[2 * i],     ph[0], ph[1], ph[2], ph[3], vl0, vl1);
                mma16816(ofr[2 * i],     pl[0], pl[1], pl[2], pl[3], vh0, vh1);
                mma16816(ofr[2 * i + 1], ph[0], ph[1], ph[2], ph[3], vh2, vh3);
                mma16816(ofr[2 * i + 1], ph[0], ph[1], ph[2], ph[3], vl2, vl3);
                mma16816(ofr[2 * i + 1], pl[0], pl[1], pl[2], pl[3], vh2, vh3);
            }
        }

        __syncthreads();
        if (it + 2 < NTILES) {
            const size_t tb = tile_base0 + (size_t)(it + 2) * TILE_BYTES;
            const uint32_t dst = smu + bufb;
            #pragma unroll
            for (int r = 0; r < 4; r++) {
                const int off = r * 2048 + tid * 16;
                cpasync16(dst + off,         gKH + tb + off);
                cpasync16(dst + 8192 + off,  gKL + tb + off);
                cpasync16(dst + 16384 + off, gVH + tb + off);
                cpasync16(dst + 24576 + off, gVL + tb + off);
            }
        }
        asm volatile("cp.async.commit_group;");
    }

    // ---- epilogue ----
    const float inv0 = 1.0f / lrow[0];
    const float inv1 = 1.0f / lrow[1];
    #pragma unroll
    for (int j = 0; j < 8; j++) {
        const int d = 8 * j + cq;
        float2 w0 = make_float2(ofr[j][0] * inv0, ofr[j][1] * inv0);
        float2 w1 = make_float2(ofr[j][2] * inv1, ofr[j][3] * inv1);
        *reinterpret_cast<float2*>(gout + ((size_t)(b * S + rr0)     * H + h) * D + d) = w0;
        *reinterpret_cast<float2*>(gout + ((size_t)(b * S + rr0 + 8) * H + h) * D + d) = w1;
    }
}

extern "C" void kernel_launch(void* const* d_in, const int* in_sizes, int n_in,
                              void* d_out, int out_size) {
    const float* q    = (const float*)d_in[0];
    const float* k    = (const float*)d_in[1];
    const float* v    = (const float*)d_in[2];
    const float* bias = (const float*)d_in[3];
    const int*   mask = (const int*)d_in[4];
    float* out = (float*)d_out;

    split_kv_kernel<<<(B * H * S * 16) / 256, 256>>>(k, v);
    pack_mask_kernel<<<(B * S * NTILES * 32) / 256, 256>>>(mask);

    cudaFuncSetAttribute(attn_mma_kernel,
                         cudaFuncAttributeMaxDynamicSharedMemorySize, SMEM_BYTES);
    dim3 grid(B * H, S / TQ);
    attn_mma_kernel<<<grid, NT, SMEM_BYTES>>>(q, bias, out);
}

// round 13
// speedup vs baseline: 4.6826x; 1.0685x over previous
#include <cuda_runtime.h>
#include <cuda_bf16.h>
#include <cuda_fp16.h>
#include <cstdint>

namespace {
constexpr int B  = 2;
constexpr int S  = 2048;
constexpr int H  = 16;
constexpr int D  = 64;
constexpr int TQ = 64;
constexpr int TK = 64;
constexpr int NT = 128;   // 4 warps
constexpr int HD = H * D;
constexpr int NTILES = S / TK;     // 32
constexpr int TILE_BYTES = 64 * 128;
constexpr int BUF = 32768;
constexpr int SMEM_BYTES = 2 * BUF;
constexpr float LOG2E = 1.4426950408889634f;
}

// Pre-split, pre-swizzled tiles: K = bf16 hi/lo, V = fp16 hi/lo. [bh][tile] 8KB blocks.
__device__ __align__(16) unsigned char gKH[(size_t)B * H * NTILES * TILE_BYTES];
__device__ __align__(16) unsigned char gKL[(size_t)B * H * NTILES * TILE_BYTES];
__device__ __align__(16) unsigned char gVH[(size_t)B * H * NTILES * TILE_BYTES];
__device__ __align__(16) unsigned char gVL[(size_t)B * H * NTILES * TILE_BYTES];
// Packed mask: [B*S][NTILES] uint64
__device__ __align__(16) unsigned long long gPM[(size_t)B * S * NTILES];

__device__ __forceinline__ uint32_t swz(uint32_t off) { return off ^ ((off >> 3) & 0x70); }

__device__ __forceinline__ void cpasync16(uint32_t dst, const void* src) {
    asm volatile("cp.async.cg.shared.global [%0], [%1], 16;" :: "r"(dst), "l"(src));
}
__device__ __forceinline__ void ldsm4(uint32_t& r0, uint32_t& r1, uint32_t& r2, uint32_t& r3, uint32_t a) {
    asm volatile("ldmatrix.sync.aligned.m8n8.x4.shared.b16 {%0,%1,%2,%3},[%4];"
                 : "=r"(r0), "=r"(r1), "=r"(r2), "=r"(r3) : "r"(a));
}
__device__ __forceinline__ void ldsm4t(uint32_t& r0, uint32_t& r1, uint32_t& r2, uint32_t& r3, uint32_t a) {
    asm volatile("ldmatrix.sync.aligned.m8n8.x4.trans.shared.b16 {%0,%1,%2,%3},[%4];"
                 : "=r"(r0), "=r"(r1), "=r"(r2), "=r"(r3) : "r"(a));
}
// bf16 MMA (QK path)
__device__ __forceinline__ void mma_bf(float c[4], uint32_t a0, uint32_t a1, uint32_t a2, uint32_t a3,
                                       uint32_t b0, uint32_t b1) {
    asm volatile("mma.sync.aligned.m16n8k16.row.col.f32.bf16.bf16.f32 "
                 "{%0,%1,%2,%3},{%4,%5,%6,%7},{%8,%9},{%0,%1,%2,%3};"
                 : "+f"(c[0]), "+f"(c[1]), "+f"(c[2]), "+f"(c[3])
                 : "r"(a0), "r"(a1), "r"(a2), "r"(a3), "r"(b0), "r"(b1));
}
// fp16 MMA (PV path)
__device__ __forceinline__ void mma_fp(float c[4], uint32_t a0, uint32_t a1, uint32_t a2, uint32_t a3,
                                       uint32_t b0, uint32_t b1) {
    asm volatile("mma.sync.aligned.m16n8k16.row.col.f32.f16.f16.f32 "
                 "{%0,%1,%2,%3},{%4,%5,%6,%7},{%8,%9},{%0,%1,%2,%3};"
                 : "+f"(c[0]), "+f"(c[1]), "+f"(c[2]), "+f"(c[3])
                 : "r"(a0), "r"(a1), "r"(a2), "r"(a3), "r"(b0), "r"(b1));
}
__device__ __forceinline__ float ex2(float x) {
    float y; asm("ex2.approx.f32 %0, %1;" : "=f"(y) : "f"(x)); return y;
}
// packed f16x2: first src -> high half
__device__ __forceinline__ uint32_t cvt_f16x2(float hi, float lo) {
    uint32_t r; asm("cvt.rn.f16x2.f32 %0, %1, %2;" : "=r"(r) : "f"(hi), "f"(lo)); return r;
}
__device__ __forceinline__ uint32_t pack_bf(float x, float y) {
    __nv_bfloat16 hx = __float2bfloat16_rn(x), hy = __float2bfloat16_rn(y);
    return (uint32_t)__bfloat16_as_ushort(hx) | ((uint32_t)__bfloat16_as_ushort(hy) << 16);
}
// bf16 hi/lo split (Q, K)
__device__ __forceinline__ void split4(float4 t, uint2& hv, uint2& lv) {
    __nv_bfloat16 h0 = __float2bfloat16_rn(t.x), h1 = __float2bfloat16_rn(t.y);
    __nv_bfloat16 h2 = __float2bfloat16_rn(t.z), h3 = __float2bfloat16_rn(t.w);
    hv.x = (uint32_t)__bfloat16_as_ushort(h0) | ((uint32_t)__bfloat16_as_ushort(h1) << 16);
    hv.y = (uint32_t)__bfloat16_as_ushort(h2) | ((uint32_t)__bfloat16_as_ushort(h3) << 16);
    lv.x = pack_bf(t.x - __bfloat162float(h0), t.y - __bfloat162float(h1));
    lv.y = pack_bf(t.z - __bfloat162float(h2), t.w - __bfloat162float(h3));
}
// fp16 hi/lo split (V)
__device__ __forceinline__ void split4h(float4 t, uint2& hv, uint2& lv) {
    __half h0 = __float2half_rn(t.x), h1 = __float2half_rn(t.y);
    __half h2 = __float2half_rn(t.z), h3 = __float2half_rn(t.w);
    hv.x = (uint32_t)__half_as_ushort(h0) | ((uint32_t)__half_as_ushort(h1) << 16);
    hv.y = (uint32_t)__half_as_ushort(h2) | ((uint32_t)__half_as_ushort(h3) << 16);
    __half l0 = __float2half_rn(t.x - __half2float(h0));
    __half l1 = __float2half_rn(t.y - __half2float(h1));
    __half l2 = __float2half_rn(t.z - __half2float(h2));
    __half l3 = __float2half_rn(t.w - __half2float(h3));
    lv.x = (uint32_t)__half_as_ushort(l0) | ((uint32_t)__half_as_ushort(l1) << 16);
    lv.y = (uint32_t)__half_as_ushort(l2) | ((uint32_t)__half_as_ushort(l3) << 16);
}

// ---- prepass A: K -> bf16 split, V -> fp16 split; swizzled 8KB tile blocks ----
__global__ void __launch_bounds__(256)
split_kv_kernel(const float* __restrict__ gk, const float* __restrict__ gv)
{
    const int idx = blockIdx.x * 256 + threadIdx.x;
    const int c16 = idx & 15;
    const int s   = (idx >> 4) & (S - 1);
    const int bh  = idx >> 15;
    const int b = bh >> 4, h = bh & 15;

    const size_t gsrc = ((size_t)(b * S + s) * H + h) * D + c16 * 4;
    const float4 kt = *reinterpret_cast<const float4*>(gk + gsrc);
    const float4 vt = *reinterpret_cast<const float4*>(gv + gsrc);

    const size_t base = ((size_t)(bh * NTILES + (s >> 6)) << 13)
                      + swz((uint32_t)((s & 63) * 128 + c16 * 8));
    uint2 hv, lv;
    split4(kt, hv, lv);
    *reinterpret_cast<uint2*>(gKH + base) = hv;
    *reinterpret_cast<uint2*>(gKL + base) = lv;
    split4h(vt, hv, lv);
    *reinterpret_cast<uint2*>(gVH + base) = hv;
    *reinterpret_cast<uint2*>(gVL + base) = lv;
}

// ---- prepass B: pack mask into uint64 bitmaps ----
__global__ void __launch_bounds__(256)
pack_mask_kernel(const int* __restrict__ gmask)
{
    const int gw   = (blockIdx.x * 256 + threadIdx.x) >> 5;
    const int lane = threadIdx.x & 31;
    const int row   = gw >> 5;
    const int chunk = gw & 31;
    const int* mr = gmask + (size_t)row * S + chunk * 64;
    const unsigned lo = __ballot_sync(0xffffffffu, mr[lane]      != 0);
    const unsigned hi = __ballot_sync(0xffffffffu, mr[lane + 32] != 0);
    if (lane == 0)
        gPM[(size_t)row * NTILES + chunk] = ((unsigned long long)hi << 32) | lo;
}

__global__ void __launch_bounds__(NT, 3)
attn_mma_kernel(const float* __restrict__ gq, const float* __restrict__ gbias,
                float* __restrict__ gout)
{
    extern __shared__ char smem[];
    const uint32_t smu = (uint32_t)__cvta_generic_to_shared(smem);

    const int tid  = threadIdx.x;
    const int lane = tid & 31;
    const int w    = tid >> 5;
    const int bh   = blockIdx.x;
    const int b    = bh >> 4;
    const int h    = bh & 15;
    const int q0   = blockIdx.y * TQ;

    const int sub = lane >> 3, lr = lane & 7;
    const int a_row = 16 * w + lr + ((sub & 1) << 3);
    const int a_ca  = sub >> 1;
    const int b_ro  = lr + ((sub >> 1) << 3);
    const int b_ca  = sub & 1;
    const int v_ro  = lr + ((sub & 1) << 3);
    const int v_ca  = sub >> 1;

    const size_t tile_base0 = (size_t)(bh * NTILES) << 13;

    // tile0 copy into buf0 (overlaps Q staging)
    {
        const uint32_t dst = smu;
        #pragma unroll
        for (int r = 0; r < 4; r++) {
            const int off = r * 2048 + tid * 16;
            cpasync16(dst + off,         gKH + tile_base0 + off);
            cpasync16(dst + 8192 + off,  gKL + tile_base0 + off);
            cpasync16(dst + 16384 + off, gVH + tile_base0 + off);
            cpasync16(dst + 24576 + off, gVL + tile_base0 + off);
        }
    }
    asm volatile("cp.async.commit_group;");

    // ---- stage Q (x 8*log2e, bf16 split) into buf1, take register fragments ----
    {
        const float* qb = gq + ((size_t)(b * S + q0) * H + h) * D;
        const float qs = 8.0f * LOG2E;
        #pragma unroll
        for (int r = 0; r < 8; r++) {
            const int idx = r * NT + tid;
            const int row = idx >> 4, c16 = idx & 15;
            float4 t = *reinterpret_cast<const float4*>(qb + (size_t)row * HD + c16 * 4);
            t.x *= qs; t.y *= qs; t.z *= qs; t.w *= qs;
            uint2 hv, lv;
            split4(t, hv, lv);
            const uint32_t so = swz((uint32_t)(row * 128 + c16 * 8));
            *reinterpret_cast<uint2*>(smem + BUF + so)        = hv;
            *reinterpret_cast<uint2*>(smem + BUF + 8192 + so) = lv;
        }
    }
    __syncthreads();

    uint32_t qh[4][4], ql[4][4];
    #pragma unroll
    for (int ks = 0; ks < 4; ks++) {
        const uint32_t off = swz((uint32_t)(a_row * 128 + (2 * ks + a_ca) * 16));
        ldsm4(qh[ks][0], qh[ks][1], qh[ks][2], qh[ks][3], smu + BUF + off);
        ldsm4(ql[ks][0], ql[ks][1], ql[ks][2], ql[ks][3], smu + BUF + 8192 + off);
    }
    __syncthreads();

    // tile1 copy into buf1
    {
        const size_t tb = tile_base0 + TILE_BYTES;
        const uint32_t dst = smu + BUF;
        #pragma unroll
        for (int r = 0; r < 4; r++) {
            const int off = r * 2048 + tid * 16;
            cpasync16(dst + off,         gKH + tb + off);
            cpasync16(dst + 8192 + off,  gKL + tb + off);
            cpasync16(dst + 16384 + off, gVH + tb + off);
            cpasync16(dst + 24576 + off, gVL + tb + off);
        }
    }
    asm volatile("cp.async.commit_group;");

    float ofr[8][4];
    #pragma unroll
    for (int j = 0; j < 8; j++)
        #pragma unroll
        for (int e = 0; e < 4; e++) ofr[j][e] = 0.f;
    float mrow[2] = {-1e30f, -1e30f};   // log2-domain running max
    float lrow[2] = {0.f, 0.f};

    const int rr0 = q0 + 16 * w + (lane >> 2);
    const int cq  = (lane & 3) * 2;
    const unsigned long long* pm0 = gPM + (size_t)(b * S + rr0) * NTILES;
    const unsigned long long* pm1 = gPM + (size_t)(b * S + rr0 + 8) * NTILES;

    for (int it = 0; it < NTILES; it++) {
        const int k0 = it * TK;
        const uint32_t bufb = (uint32_t)(it & 1) * BUF;
        const uint32_t KHI = bufb, KLO = bufb + 8192, VHI = bufb + 16384, VLO = bufb + 24576;

        asm volatile("cp.async.wait_group 1;");
        __syncthreads();

        const unsigned long long mw[2] = {pm0[it], pm1[it]};
        float2 bfr0[4][2];
        #pragma unroll
        for (int j = 0; j < 4; j++)
            #pragma unroll
            for (int p = 0; p < 2; p++)
                bfr0[j][p] = *reinterpret_cast<const float2*>(
                    gbias + ((size_t)bh * S + rr0 + 8 * p) * S + k0 + 8 * j + cq);

        float sfr[8][4];
        #pragma unroll
        for (int j = 0; j < 8; j++)
            #pragma unroll
            for (int e = 0; e < 4; e++) sfr[j][e] = 0.f;

        // ---- QK keys 0..31 (bf16 3-term) ----
        #pragma unroll
        for (int ks = 0; ks < 4; ks++)
            #pragma unroll
            for (int i = 0; i < 2; i++) {
                const uint32_t off = swz((uint32_t)((16 * i + b_ro) * 128 + (2 * ks + b_ca) * 16));
                uint32_t kh0, kh1, kh2, kh3, kl0, kl1, kl2, kl3;
                ldsm4(kh0, kh1, kh2, kh3, smu + KHI + off);
                ldsm4(kl0, kl1, kl2, kl3, smu + KLO + off);
                mma_bf(sfr[2 * i],     qh[ks][0], qh[ks][1], qh[ks][2], qh[ks][3], kh0, kh1);
                mma_bf(sfr[2 * i],     qh[ks][0], qh[ks][1], qh[ks][2], qh[ks][3], kl0, kl1);
                mma_bf(sfr[2 * i],     ql[ks][0], ql[ks][1], ql[ks][2], ql[ks][3], kh0, kh1);
                mma_bf(sfr[2 * i + 1], qh[ks][0], qh[ks][1], qh[ks][2], qh[ks][3], kh2, kh3);
                mma_bf(sfr[2 * i + 1], qh[ks][0], qh[ks][1], qh[ks][2], qh[ks][3], kl2, kl3);
                mma_bf(sfr[2 * i + 1], ql[ks][0], ql[ks][1], ql[ks][2], ql[ks][3], kh2, kh3);
            }

        float2 bfr1[4][2];
        #pragma unroll
        for (int j = 0; j < 4; j++)
            #pragma unroll
            for (int p = 0; p < 2; p++)
                bfr1[j][p] = *reinterpret_cast<const float2*>(
                    gbias + ((size_t)bh * S + rr0 + 8 * p) * S + k0 + 32 + 8 * j + cq);

        // ---- QK keys 32..63 ----
        #pragma unroll
        for (int ks = 0; ks < 4; ks++)
            #pragma unroll
            for (int i = 2; i < 4; i++) {
                const uint32_t off = swz((uint32_t)((16 * i + b_ro) * 128 + (2 * ks + b_ca) * 16));
                uint32_t kh0, kh1, kh2, kh3, kl0, kl1, kl2, kl3;
                ldsm4(kh0, kh1, kh2, kh3, smu + KHI + off);
                ldsm4(kl0, kl1, kl2, kl3, smu + KLO + off);
                mma_bf(sfr[2 * i],     qh[ks][0], qh[ks][1], qh[ks][2], qh[ks][3], kh0, kh1);
                mma_bf(sfr[2 * i],     qh[ks][0], qh[ks][1], qh[ks][2], qh[ks][3], kl0, kl1);
                mma_bf(sfr[2 * i],     ql[ks][0], ql[ks][1], ql[ks][2], ql[ks][3], kh0, kh1);
                mma_bf(sfr[2 * i + 1], qh[ks][0], qh[ks][1], qh[ks][2], qh[ks][3], kh2, kh3);
                mma_bf(sfr[2 * i + 1], qh[ks][0], qh[ks][1], qh[ks][2], qh[ks][3], kl2, kl3);
                mma_bf(sfr[2 * i + 1], ql[ks][0], ql[ks][1], ql[ks][2], ql[ks][3], kh2, kh3);
            }

        // ---- bias (x log2e via FMA) + packed mask ----
        #pragma unroll
        for (int j = 0; j < 8; j++) {
            const float2* bp = (j < 4) ? bfr0[j] : bfr1[j - 4];
            const int base = 8 * j + cq;
            #pragma unroll
            for (int p = 0; p < 2; p++) {
                const unsigned mb = (unsigned)(mw[p] >> base);
                sfr[j][2 * p]     = (mb & 1u) ? 0.0f : fmaf(bp[p].x, LOG2E, sfr[j][2 * p]);
                sfr[j][2 * p + 1] = (mb & 2u) ? 0.0f : fmaf(bp[p].y, LOG2E, sfr[j][2 * p + 1]);
            }
        }

        // ---- single online softmax (log2 domain, EX2 only) ----
        float mold[2], mnew2[2], rs2[2];
        #pragma unroll
        for (int p = 0; p < 2; p++) {
            float mx = -1e30f;
            #pragma unroll
            for (int j = 0; j < 8; j++)
                mx = fmaxf(mx, fmaxf(sfr[j][2 * p], sfr[j][2 * p + 1]));
            mx = fmaxf(mx, __shfl_xor_sync(0xffffffffu, mx, 1));
            mx = fmaxf(mx, __shfl_xor_sync(0xffffffffu, mx, 2));
            mold[p] = mrow[p];
            const float mnew = fmaxf(mrow[p], mx);
            mrow[p] = mnew;
            mnew2[p] = mnew;

            float rs = 0.f;
            #pragma unroll
            for (int j = 0; j < 8; j++) {
                const float e0 = ex2(sfr[j][2 * p]     - mnew);
                const float e1 = ex2(sfr[j][2 * p + 1] - mnew);
                sfr[j][2 * p] = e0; sfr[j][2 * p + 1] = e1;
                rs += e0 + e1;
            }
            rs += __shfl_xor_sync(0xffffffffu, rs, 1);
            rs += __shfl_xor_sync(0xffffffffu, rs, 2);
            rs2[p] = rs;
        }

        // lazy rescale (warp-uniform skip)
        const bool moved = (mnew2[0] != mold[0]) || (mnew2[1] != mold[1]);
        if (__any_sync(0xffffffffu, moved)) {
            const float c0 = ex2(mold[0] - mnew2[0]);
            const float c1 = ex2(mold[1] - mnew2[1]);
            lrow[0] = lrow[0] * c0 + rs2[0];
            lrow[1] = lrow[1] * c1 + rs2[1];
            #pragma unroll
            for (int j = 0; j < 8; j++) {
                ofr[j][0] *= c0; ofr[j][1] *= c0;
                ofr[j][2] *= c1; ofr[j][3] *= c1;
            }
        } else {
            lrow[0] += rs2[0];
            lrow[1] += rs2[1];
        }

        // ---- PV: fp16 2-term (P single fp16, V hi/lo fp16) ----
        #pragma unroll
        for (int ksp = 0; ksp < 4; ksp++) {
            uint32_t ph[4];
            #pragma unroll
            for (int half = 0; half < 2; half++) {
                const int j = 2 * ksp + half;
                #pragma unroll
                for (int p = 0; p < 2; p++)
                    ph[half * 2 + p] = cvt_f16x2(sfr[j][2 * p + 1], sfr[j][2 * p]);
            }
            #pragma unroll
            for (int i = 0; i < 4; i++) {
                const uint32_t off = swz((uint32_t)((16 * ksp + v_ro) * 128 + (2 * i + v_ca) * 16));
                uint32_t vh0, vh1, vh2, vh3, vl0, vl1, vl2, vl3;
                ldsm4t(vh0, vh1, vh2, vh3, smu + VHI + off);
                ldsm4t(vl0, vl1, vl2, vl3, smu + VLO + off);
                mma_fp(ofr[2 * i],     ph[0], ph[1], ph[2], ph[3], vh0, vh1);
                mma_fp(ofr[2 * i],     ph[0], ph[1], ph[2], ph[3], vl0, vl1);
                mma_fp(ofr[2 * i + 1], ph[0], ph[1], ph[2], ph[3], vh2, vh3);
                mma_fp(ofr[2 * i + 1], ph[0], ph[1], ph[2], ph[3], vl2, vl3);
            }
        }

        __syncthreads();
        if (it + 2 < NTILES) {
            const size_t tb = tile_base0 + (size_t)(it + 2) * TILE_BYTES;
            const uint32_t dst = smu + bufb;
            #pragma unroll
            for (int r = 0; r < 4; r++) {
                const int off = r * 2048 + tid * 16;
                cpasync16(dst + off,         gKH + tb + off);
                cpasync16(dst + 8192 + off,  gKL + tb + off);
                cpasync16(dst + 16384 + off, gVH + tb + off);
                cpasync16(dst + 24576 + off, gVL + tb + off);
            }
        }
        asm volatile("cp.async.commit_group;");
    }

    // ---- epilogue ----
    const float inv0 = 1.0f / lrow[0];
    const float inv1 = 1.0f / lrow[1];
    #pragma unroll
    for (int j = 0; j < 8; j++) {
        const int d = 8 * j + cq;
        float2 w0 = make_float2(ofr[j][0] * inv0, ofr[j][1] * inv0);
        float2 w1 = make_float2(ofr[j][2] * inv1, ofr[j][3] * inv1);
        *reinterpret_cast<float2*>(gout + ((size_t)(b * S + rr0)     * H + h) * D + d) = w0;
        *reinterpret_cast<float2*>(gout + ((size_t)(b * S + rr0 + 8) * H + h) * D + d) = w1;
    }
}

extern "C" void kernel_launch(void* const* d_in, const int* in_sizes, int n_in,
                              void* d_out, int out_size) {
    const float* q    = (const float*)d_in[0];
    const float* k    = (const float*)d_in[1];
    const float* v    = (const float*)d_in[2];
    const float* bias = (const float*)d_in[3];
    const int*   mask = (const int*)d_in[4];
    float* out = (float*)d_out;

    split_kv_kernel<<<(B * H * S * 16) / 256, 256>>>(k, v);
    pack_mask_kernel<<<(B * S * NTILES * 32) / 256, 256>>>(mask);

    cudaFuncSetAttribute(attn_mma_kernel,
                         cudaFuncAttributeMaxDynamicSharedMemorySize, SMEM_BYTES);
    dim3 grid(B * H, S / TQ);
    attn_mma_kernel<<<grid, NT, SMEM_BYTES>>>(q, bias, out);
}

// round 14
// speedup vs baseline: 5.3605x; 1.1448x over previous
#include <cuda_runtime.h>
#include <cuda_bf16.h>
#include <cuda_fp16.h>
#include <cstdint>

namespace {
constexpr int B  = 2;
constexpr int S  = 2048;
constexpr int H  = 16;
constexpr int D  = 64;
constexpr int TQ = 64;
constexpr int TK = 64;
constexpr int NT = 128;   // 4 warps
constexpr int HD = H * D;
constexpr int NTILES = S / TK;     // 32
constexpr int TILE_BYTES = 64 * 128;
constexpr int BUF = 24576;          // KH 0, KL 8K, VH 16K
constexpr int SMEM_BYTES = 2 * BUF; // 48KB
constexpr float LOG2E = 1.4426950408889634f;
}

// Pre-split, pre-swizzled tiles: K = bf16 hi/lo, V = fp16 single. [bh][tile] 8KB blocks.
__device__ __align__(16) unsigned char gKH[(size_t)B * H * NTILES * TILE_BYTES];
__device__ __align__(16) unsigned char gKL[(size_t)B * H * NTILES * TILE_BYTES];
__device__ __align__(16) unsigned char gVH[(size_t)B * H * NTILES * TILE_BYTES];
// Packed mask: [B*S][NTILES] uint64
__device__ __align__(16) unsigned long long gPM[(size_t)B * S * NTILES];

__device__ __forceinline__ uint32_t swz(uint32_t off) { return off ^ ((off >> 3) & 0x70); }

__device__ __forceinline__ void cpasync16(uint32_t dst, const void* src) {
    asm volatile("cp.async.cg.shared.global [%0], [%1], 16;" :: "r"(dst), "l"(src));
}
__device__ __forceinline__ void ldsm4(uint32_t& r0, uint32_t& r1, uint32_t& r2, uint32_t& r3, uint32_t a) {
    asm volatile("ldmatrix.sync.aligned.m8n8.x4.shared.b16 {%0,%1,%2,%3},[%4];"
                 : "=r"(r0), "=r"(r1), "=r"(r2), "=r"(r3) : "r"(a));
}
__device__ __forceinline__ void ldsm4t(uint32_t& r0, uint32_t& r1, uint32_t& r2, uint32_t& r3, uint32_t a) {
    asm volatile("ldmatrix.sync.aligned.m8n8.x4.trans.shared.b16 {%0,%1,%2,%3},[%4];"
                 : "=r"(r0), "=r"(r1), "=r"(r2), "=r"(r3) : "r"(a));
}
// bf16 MMA (QK path)
__device__ __forceinline__ void mma_bf(float c[4], uint32_t a0, uint32_t a1, uint32_t a2, uint32_t a3,
                                       uint32_t b0, uint32_t b1) {
    asm volatile("mma.sync.aligned.m16n8k16.row.col.f32.bf16.bf16.f32 "
                 "{%0,%1,%2,%3},{%4,%5,%6,%7},{%8,%9},{%0,%1,%2,%3};"
                 : "+f"(c[0]), "+f"(c[1]), "+f"(c[2]), "+f"(c[3])
                 : "r"(a0), "r"(a1), "r"(a2), "r"(a3), "r"(b0), "r"(b1));
}
// fp16 MMA (PV path)
__device__ __forceinline__ void mma_fp(float c[4], uint32_t a0, uint32_t a1, uint32_t a2, uint32_t a3,
                                       uint32_t b0, uint32_t b1) {
    asm volatile("mma.sync.aligned.m16n8k16.row.col.f32.f16.f16.f32 "
                 "{%0,%1,%2,%3},{%4,%5,%6,%7},{%8,%9},{%0,%1,%2,%3};"
                 : "+f"(c[0]), "+f"(c[1]), "+f"(c[2]), "+f"(c[3])
                 : "r"(a0), "r"(a1), "r"(a2), "r"(a3), "r"(b0), "r"(b1));
}
__device__ __forceinline__ float ex2(float x) {
    float y; asm("ex2.approx.f32 %0, %1;" : "=f"(y) : "f"(x)); return y;
}
// packed f16x2: first src -> high half
__device__ __forceinline__ uint32_t cvt_f16x2(float hi, float lo) {
    uint32_t r; asm("cvt.rn.f16x2.f32 %0, %1, %2;" : "=r"(r) : "f"(hi), "f"(lo)); return r;
}
__device__ __forceinline__ uint32_t pack_bf(float x, float y) {
    __nv_bfloat16 hx = __float2bfloat16_rn(x), hy = __float2bfloat16_rn(y);
    return (uint32_t)__bfloat16_as_ushort(hx) | ((uint32_t)__bfloat16_as_ushort(hy) << 16);
}
// bf16 hi/lo split (Q, K)
__device__ __forceinline__ void split4(float4 t, uint2& hv, uint2& lv) {
    __nv_bfloat16 h0 = __float2bfloat16_rn(t.x), h1 = __float2bfloat16_rn(t.y);
    __nv_bfloat16 h2 = __float2bfloat16_rn(t.z), h3 = __float2bfloat16_rn(t.w);
    hv.x = (uint32_t)__bfloat16_as_ushort(h0) | ((uint32_t)__bfloat16_as_ushort(h1) << 16);
    hv.y = (uint32_t)__bfloat16_as_ushort(h2) | ((uint32_t)__bfloat16_as_ushort(h3) << 16);
    lv.x = pack_bf(t.x - __bfloat162float(h0), t.y - __bfloat162float(h1));
    lv.y = pack_bf(t.z - __bfloat162float(h2), t.w - __bfloat162float(h3));
}

// ---- prepass A: K -> bf16 split, V -> fp16 single; swizzled 8KB tile blocks ----
__global__ void __launch_bounds__(256)
split_kv_kernel(const float* __restrict__ gk, const float* __restrict__ gv)
{
    const int idx = blockIdx.x * 256 + threadIdx.x;
    const int c16 = idx & 15;
    const int s   = (idx >> 4) & (S - 1);
    const int bh  = idx >> 15;
    const int b = bh >> 4, h = bh & 15;

    const size_t gsrc = ((size_t)(b * S + s) * H + h) * D + c16 * 4;
    const float4 kt = *reinterpret_cast<const float4*>(gk + gsrc);
    const float4 vt = *reinterpret_cast<const float4*>(gv + gsrc);

    const size_t base = ((size_t)(bh * NTILES + (s >> 6)) << 13)
                      + swz((uint32_t)((s & 63) * 128 + c16 * 8));
    uint2 hv, lv;
    split4(kt, hv, lv);
    *reinterpret_cast<uint2*>(gKH + base) = hv;
    *reinterpret_cast<uint2*>(gKL + base) = lv;
    uint2 vv;
    vv.x = cvt_f16x2(vt.y, vt.x);
    vv.y = cvt_f16x2(vt.w, vt.z);
    *reinterpret_cast<uint2*>(gVH + base) = vv;
}

// ---- prepass B: pack mask into uint64 bitmaps ----
__global__ void __launch_bounds__(256)
pack_mask_kernel(const int* __restrict__ gmask)
{
    const int gw   = (blockIdx.x * 256 + threadIdx.x) >> 5;
    const int lane = threadIdx.x & 31;
    const int row   = gw >> 5;
    const int chunk = gw & 31;
    const int* mr = gmask + (size_t)row * S + chunk * 64;
    const unsigned lo = __ballot_sync(0xffffffffu, mr[lane]      != 0);
    const unsigned hi = __ballot_sync(0xffffffffu, mr[lane + 32] != 0);
    if (lane == 0)
        gPM[(size_t)row * NTILES + chunk] = ((unsigned long long)hi << 32) | lo;
}

__device__ __forceinline__ void copy_tile(uint32_t dst, const size_t tb, int tid) {
    #pragma unroll
    for (int r = 0; r < 4; r++) {
        const int off = r * 2048 + tid * 16;
        cpasync16(dst + off,         gKH + tb + off);
        cpasync16(dst + 8192 + off,  gKL + tb + off);
        cpasync16(dst + 16384 + off, gVH + tb + off);
    }
}

__global__ void __launch_bounds__(NT, 3)
attn_mma_kernel(const float* __restrict__ gq, const float* __restrict__ gbias,
                float* __restrict__ gout)
{
    extern __shared__ char smem[];
    const uint32_t smu = (uint32_t)__cvta_generic_to_shared(smem);

    const int tid  = threadIdx.x;
    const int lane = tid & 31;
    const int w    = tid >> 5;
    const int bh   = blockIdx.x;
    const int b    = bh >> 4;
    const int h    = bh & 15;
    const int q0   = blockIdx.y * TQ;

    const int sub = lane >> 3, lr = lane & 7;
    const int a_row = 16 * w + lr + ((sub & 1) << 3);
    const int a_ca  = sub >> 1;
    const int b_ro  = lr + ((sub >> 1) << 3);
    const int b_ca  = sub & 1;
    const int v_ro  = lr + ((sub & 1) << 3);
    const int v_ca  = sub >> 1;

    const size_t tile_base0 = (size_t)(bh * NTILES) << 13;

    // tile0 copy into buf0 (overlaps Q staging)
    copy_tile(smu, tile_base0, tid);
    asm volatile("cp.async.commit_group;");

    // ---- stage Q (x 8*log2e, bf16 split) into buf1, take register fragments ----
    {
        const float* qb = gq + ((size_t)(b * S + q0) * H + h) * D;
        const float qs = 8.0f * LOG2E;
        #pragma unroll
        for (int r = 0; r < 8; r++) {
            const int idx = r * NT + tid;
            const int row = idx >> 4, c16 = idx & 15;
            float4 t = *reinterpret_cast<const float4*>(qb + (size_t)row * HD + c16 * 4);
            t.x *= qs; t.y *= qs; t.z *= qs; t.w *= qs;
            uint2 hv, lv;
            split4(t, hv, lv);
            const uint32_t so = swz((uint32_t)(row * 128 + c16 * 8));
            *reinterpret_cast<uint2*>(smem + BUF + so)        = hv;
            *reinterpret_cast<uint2*>(smem + BUF + 8192 + so) = lv;
        }
    }
    __syncthreads();

    uint32_t qh[4][4], ql[4][4];
    #pragma unroll
    for (int ks = 0; ks < 4; ks++) {
        const uint32_t off = swz((uint32_t)(a_row * 128 + (2 * ks + a_ca) * 16));
        ldsm4(qh[ks][0], qh[ks][1], qh[ks][2], qh[ks][3], smu + BUF + off);
        ldsm4(ql[ks][0], ql[ks][1], ql[ks][2], ql[ks][3], smu + BUF + 8192 + off);
    }
    __syncthreads();

    // tile1 copy into buf1
    copy_tile(smu + BUF, tile_base0 + TILE_BYTES, tid);
    asm volatile("cp.async.commit_group;");

    float ofr[8][4];
    #pragma unroll
    for (int j = 0; j < 8; j++)
        #pragma unroll
        for (int e = 0; e < 4; e++) ofr[j][e] = 0.f;
    float mrow[2] = {-1e30f, -1e30f};   // log2-domain running max
    float lrow[2] = {0.f, 0.f};

    const int rr0 = q0 + 16 * w + (lane >> 2);
    const int cq  = (lane & 3) * 2;
    const unsigned long long* pm0 = gPM + (size_t)(b * S + rr0) * NTILES;
    const unsigned long long* pm1 = gPM + (size_t)(b * S + rr0 + 8) * NTILES;

    for (int it = 0; it < NTILES; it++) {
        const int k0 = it * TK;
        const uint32_t bufb = (uint32_t)(it & 1) * BUF;
        const uint32_t KHI = bufb, KLO = bufb + 8192, VHI = bufb + 16384;

        asm volatile("cp.async.wait_group 1;");
        __syncthreads();

        const unsigned long long mw[2] = {pm0[it], pm1[it]};
        float2 bfr0[4][2];
        #pragma unroll
        for (int j = 0; j < 4; j++)
            #pragma unroll
            for (int p = 0; p < 2; p++)
                bfr0[j][p] = *reinterpret_cast<const float2*>(
                    gbias + ((size_t)bh * S + rr0 + 8 * p) * S + k0 + 8 * j + cq);

        float sfr[8][4];
        #pragma unroll
        for (int j = 0; j < 8; j++)
            #pragma unroll
            for (int e = 0; e < 4; e++) sfr[j][e] = 0.f;

        // ---- QK keys 0..31 (bf16 3-term) ----
        #pragma unroll
        for (int ks = 0; ks < 4; ks++)
            #pragma unroll
            for (int i = 0; i < 2; i++) {
                const uint32_t off = swz((uint32_t)((16 * i + b_ro) * 128 + (2 * ks + b_ca) * 16));
                uint32_t kh0, kh1, kh2, kh3, kl0, kl1, kl2, kl3;
                ldsm4(kh0, kh1, kh2, kh3, smu + KHI + off);
                ldsm4(kl0, kl1, kl2, kl3, smu + KLO + off);
                mma_bf(sfr[2 * i],     qh[ks][0], qh[ks][1], qh[ks][2], qh[ks][3], kh0, kh1);
                mma_bf(sfr[2 * i],     qh[ks][0], qh[ks][1], qh[ks][2], qh[ks][3], kl0, kl1);
                mma_bf(sfr[2 * i],     ql[ks][0], ql[ks][1], ql[ks][2], ql[ks][3], kh0, kh1);
                mma_bf(sfr[2 * i + 1], qh[ks][0], qh[ks][1], qh[ks][2], qh[ks][3], kh2, kh3);
                mma_bf(sfr[2 * i + 1], qh[ks][0], qh[ks][1], qh[ks][2], qh[ks][3], kl2, kl3);
                mma_bf(sfr[2 * i + 1], ql[ks][0], ql[ks][1], ql[ks][2], ql[ks][3], kh2, kh3);
            }

        float2 bfr1[4][2];
        #pragma unroll
        for (int j = 0; j < 4; j++)
            #pragma unroll
            for (int p = 0; p < 2; p++)
                bfr1[j][p] = *reinterpret_cast<const float2*>(
                    gbias + ((size_t)bh * S + rr0 + 8 * p) * S + k0 + 32 + 8 * j + cq);

        // ---- QK keys 32..63 ----
        #pragma unroll
        for (int ks = 0; ks < 4; ks++)
            #pragma unroll
            for (int i = 2; i < 4; i++) {
                const uint32_t off = swz((uint32_t)((16 * i + b_ro) * 128 + (2 * ks + b_ca) * 16));
                uint32_t kh0, kh1, kh2, kh3, kl0, kl1, kl2, kl3;
                ldsm4(kh0, kh1, kh2, kh3, smu + KHI + off);
                ldsm4(kl0, kl1, kl2, kl3, smu + KLO + off);
                mma_bf(sfr[2 * i],     qh[ks][0], qh[ks][1], qh[ks][2], qh[ks][3], kh0, kh1);
                mma_bf(sfr[2 * i],     qh[ks][0], qh[ks][1], qh[ks][2], qh[ks][3], kl0, kl1);
                mma_bf(sfr[2 * i],     ql[ks][0], ql[ks][1], ql[ks][2], ql[ks][3], kh0, kh1);
                mma_bf(sfr[2 * i + 1], qh[ks][0], qh[ks][1], qh[ks][2], qh[ks][3], kh2, kh3);
                mma_bf(sfr[2 * i + 1], qh[ks][0], qh[ks][1], qh[ks][2], qh[ks][3], kl2, kl3);
                mma_bf(sfr[2 * i + 1], ql[ks][0], ql[ks][1], ql[ks][2], ql[ks][3], kh2, kh3);
            }

        // ---- bias (x log2e via FMA) + packed mask ----
        #pragma unroll
        for (int j = 0; j < 8; j++) {
            const float2* bp = (j < 4) ? bfr0[j] : bfr1[j - 4];
            const int base = 8 * j + cq;
            #pragma unroll
            for (int p = 0; p < 2; p++) {
                const unsigned mb = (unsigned)(mw[p] >> base);
                sfr[j][2 * p]     = (mb & 1u) ? 0.0f : fmaf(bp[p].x, LOG2E, sfr[j][2 * p]);
                sfr[j][2 * p + 1] = (mb & 2u) ? 0.0f : fmaf(bp[p].y, LOG2E, sfr[j][2 * p + 1]);
            }
        }

        // ---- single online softmax (log2 domain, EX2 only) ----
        float mold[2], mnew2[2], rs2[2];
        #pragma unroll
        for (int p = 0; p < 2; p++) {
            float mx = -1e30f;
            #pragma unroll
            for (int j = 0; j < 8; j++)
                mx = fmaxf(mx, fmaxf(sfr[j][2 * p], sfr[j][2 * p + 1]));
            mx = fmaxf(mx, __shfl_xor_sync(0xffffffffu, mx, 1));
            mx = fmaxf(mx, __shfl_xor_sync(0xffffffffu, mx, 2));
            mold[p] = mrow[p];
            const float mnew = fmaxf(mrow[p], mx);
            mrow[p] = mnew;
            mnew2[p] = mnew;

            float rs = 0.f;
            #pragma unroll
            for (int j = 0; j < 8; j++) {
                const float e0 = ex2(sfr[j][2 * p]     - mnew);
                const float e1 = ex2(sfr[j][2 * p + 1] - mnew);
                sfr[j][2 * p] = e0; sfr[j][2 * p + 1] = e1;
                rs += e0 + e1;
            }
            rs += __shfl_xor_sync(0xffffffffu, rs, 1);
            rs += __shfl_xor_sync(0xffffffffu, rs, 2);
            rs2[p] = rs;
        }

        // lazy rescale (warp-uniform skip)
        const bool moved = (mnew2[0] != mold[0]) || (mnew2[1] != mold[1]);
        if (__any_sync(0xffffffffu, moved)) {
            const float c0 = ex2(mold[0] - mnew2[0]);
            const float c1 = ex2(mold[1] - mnew2[1]);
            lrow[0] = lrow[0] * c0 + rs2[0];
            lrow[1] = lrow[1] * c1 + rs2[1];
            #pragma unroll
            for (int j = 0; j < 8; j++) {
                ofr[j][0] *= c0; ofr[j][1] *= c0;
                ofr[j][2] *= c1; ofr[j][3] *= c1;
            }
        } else {
            lrow[0] += rs2[0];
            lrow[1] += rs2[1];
        }

        // ---- PV: fp16 1-term (P single fp16, V single fp16) ----
        #pragma unroll
        for (int ksp = 0; ksp < 4; ksp++) {
            uint32_t ph[4];
            #pragma unroll
            for (int half = 0; half < 2; half++) {
                const int j = 2 * ksp + half;
                #pragma unroll
                for (int p = 0; p < 2; p++)
                    ph[half * 2 + p] = cvt_f16x2(sfr[j][2 * p + 1], sfr[j][2 * p]);
            }
            #pragma unroll
            for (int i = 0; i < 4; i++) {
                const uint32_t off = swz((uint32_t)((16 * ksp + v_ro) * 128 + (2 * i + v_ca) * 16));
                uint32_t vh0, vh1, vh2, vh3;
                ldsm4t(vh0, vh1, vh2, vh3, smu + VHI + off);
                mma_fp(ofr[2 * i],     ph[0], ph[1], ph[2], ph[3], vh0, vh1);
                mma_fp(ofr[2 * i + 1], ph[0], ph[1], ph[2], ph[3], vh2, vh3);
            }
        }

        __syncthreads();
        if (it + 2 < NTILES)
            copy_tile(smu + bufb, tile_base0 + (size_t)(it + 2) * TILE_BYTES, tid);
        asm volatile("cp.async.commit_group;");
    }

    // ---- epilogue ----
    const float inv0 = 1.0f / lrow[0];
    const float inv1 = 1.0f / lrow[1];
    #pragma unroll
    for (int j = 0; j < 8; j++) {
        const int d = 8 * j + cq;
        float2 w0 = make_float2(ofr[j][0] * inv0, ofr[j][1] * inv0);
        float2 w1 = make_float2(ofr[j][2] * inv1, ofr[j][3] * inv1);
        *reinterpret_cast<float2*>(gout + ((size_t)(b * S + rr0)     * H + h) * D + d) = w0;
        *reinterpret_cast<float2*>(gout + ((size_t)(b * S + rr0 + 8) * H + h) * D + d) = w1;
    }
}

extern "C" void kernel_launch(void* const* d_in, const int* in_sizes, int n_in,
                              void* d_out, int out_size) {
    const float* q    = (const float*)d_in[0];
    const float* k    = (const float*)d_in[1];
    const float* v    = (const float*)d_in[2];
    const float* bias = (const float*)d_in[3];
    const int*   mask = (const int*)d_in[4];
    float* out = (float*)d_out;

    split_kv_kernel<<<(B * H * S * 16) / 256, 256>>>(k, v);
    pack_mask_kernel<<<(B * S * NTILES * 32) / 256, 256>>>(mask);

    cudaFuncSetAttribute(attn_mma_kernel,
                         cudaFuncAttributeMaxDynamicSharedMemorySize, SMEM_BYTES);
    dim3 grid(B * H, S / TQ);
    attn_mma_kernel<<<grid, NT, SMEM_BYTES>>>(q, bias, out);
}